// round 10
// baseline (speedup 1.0000x reference)
#include <cuda_runtime.h>
#include <math.h>

// Problem dims
#define Bb 32
#define LC 2048
#define LQ 256
#define Dd 256

// GEMM tiling
#define BM 128
#define BN 128
#define KC 32
#define PAD 4

// ---------------- scratch (device globals; no allocations allowed) ----------------
__device__ float g_E[(size_t)Bb * LC * LQ];          // exp(sim), 0 at masked  (67 MB)
__device__ float g_T[(size_t)Bb * LQ * Dd];          // T = SS^T @ context      (8 MB)
__device__ float g_sc[Bb * LC];
__device__ float g_sq[Bb * LQ];
__device__ float g_rowsum_part[Bb * 2 * LC];         // per q-tile partials
__device__ float g_rowsum[Bb * LC];
__device__ float g_colsum_part[Bb * 16 * LQ];        // per c-tile partials
__device__ float g_colsum[Bb * LQ];
__device__ float g_qmean[Bb * Dd];
__device__ float g_cmean_part[Bb * 8 * Dd];
__device__ float g_cmean[Bb * Dd];
__device__ float g_tmean[Bb * Dd];
__device__ unsigned char g_cm[Bb * LC];
__device__ unsigned char g_qm[Bb * LQ];
__device__ int g_is32;

// ---------------- mask dtype detection + canonicalization ----------------
// numpy bool -> 1 byte/elem (random 0/1 bytes). If harness widened to int32,
// every element is {v,0,0,0} little-endian -> bytes at (i%4!=0) are all zero.
__global__ void k_detect(const unsigned char* __restrict__ cm) {
    if (threadIdx.x == 0 && blockIdx.x == 0) {
        int is32 = 1;
        for (int i = 0; i < 4096; i++) {
            if ((i & 3) && cm[i]) { is32 = 0; break; }
        }
        g_is32 = is32;
    }
}

__global__ void k_cvt_mask(const void* __restrict__ cm, const void* __restrict__ qm) {
    int i = blockIdx.x * 256 + threadIdx.x;
    int is32 = g_is32;
    if (i < Bb * LC) {
        g_cm[i] = is32 ? (unsigned char)(((const int*)cm)[i] != 0)
                       : (unsigned char)(((const unsigned char*)cm)[i] != 0);
    }
    if (i < Bb * LQ) {
        g_qm[i] = is32 ? (unsigned char)(((const int*)qm)[i] != 0)
                       : (unsigned char)(((const unsigned char*)qm)[i] != 0);
    }
}

// ---------------- K0a: sc = context @ wc, sq = query @ wq ----------------
__global__ void k0_rowdots(const float* __restrict__ ctx, const float* __restrict__ qry,
                           const float* __restrict__ w0) {
    int warp = (blockIdx.x * blockDim.x + threadIdx.x) >> 5;
    int lane = threadIdx.x & 31;
    const int nC = Bb * LC;
    const float* src;
    const float* wgt;
    float* dst;
    if (warp < nC) {
        src = ctx + (size_t)warp * Dd; wgt = w0; dst = g_sc + warp;
    } else {
        int r = warp - nC;
        if (r >= Bb * LQ) return;
        src = qry + (size_t)r * Dd; wgt = w0 + Dd; dst = g_sq + r;
    }
    float s = 0.f;
#pragma unroll
    for (int i = 0; i < 2; i++) {
        int idx = (lane + 32 * i) * 4;
        float4 v = *(const float4*)(src + idx);
        float4 w = *(const float4*)(wgt + idx);
        s += v.x * w.x + v.y * w.y + v.z * w.z + v.w * w.w;
    }
#pragma unroll
    for (int o = 16; o; o >>= 1) s += __shfl_xor_sync(0xffffffffu, s, o);
    if (lane == 0) *dst = s;
}

// ---------------- K0b: qmean, cmean partials ----------------
__global__ void k0_means(const float* __restrict__ ctx, const float* __restrict__ qry) {
    int b = blockIdx.x, y = blockIdx.y, d = threadIdx.x;  // 256 threads = D
    if (y == 0) {
        const float* p = qry + (size_t)b * LQ * Dd + d;
        float s0 = 0, s1 = 0, s2 = 0, s3 = 0, s4 = 0, s5 = 0, s6 = 0, s7 = 0;
        for (int q = 0; q < LQ; q += 8) {
            s0 += p[(size_t)(q + 0) * Dd]; s1 += p[(size_t)(q + 1) * Dd];
            s2 += p[(size_t)(q + 2) * Dd]; s3 += p[(size_t)(q + 3) * Dd];
            s4 += p[(size_t)(q + 4) * Dd]; s5 += p[(size_t)(q + 5) * Dd];
            s6 += p[(size_t)(q + 6) * Dd]; s7 += p[(size_t)(q + 7) * Dd];
        }
        g_qmean[b * Dd + d] = (((s0 + s1) + (s2 + s3)) + ((s4 + s5) + (s6 + s7))) * (1.0f / LQ);
    } else {
        int chunk = y - 1;  // 8 chunks of 256 context rows
        const float* p = ctx + ((size_t)b * LC + chunk * 256) * Dd + d;
        float s0 = 0, s1 = 0, s2 = 0, s3 = 0, s4 = 0, s5 = 0, s6 = 0, s7 = 0;
        for (int c = 0; c < 256; c += 8) {
            s0 += p[(size_t)(c + 0) * Dd]; s1 += p[(size_t)(c + 1) * Dd];
            s2 += p[(size_t)(c + 2) * Dd]; s3 += p[(size_t)(c + 3) * Dd];
            s4 += p[(size_t)(c + 4) * Dd]; s5 += p[(size_t)(c + 5) * Dd];
            s6 += p[(size_t)(c + 6) * Dd]; s7 += p[(size_t)(c + 7) * Dd];
        }
        g_cmean_part[((size_t)b * 8 + chunk) * Dd + d] =
            ((s0 + s1) + (s2 + s3)) + ((s4 + s5) + (s6 + s7));
    }
}

// ---------------- K1: E = exp(sim) (masked -> 0) + row/col partial sums ----------------
__global__ __launch_bounds__(256)
void k1_exp(const float* __restrict__ ctx, const float* __restrict__ qry,
            const float* __restrict__ w0) {
    int b = blockIdx.z;
    int cblk = blockIdx.x * BM;   // 16 tiles
    int qblk = blockIdx.y * BN;   // 2 tiles
    __shared__ float As[KC][BM + PAD];
    __shared__ float Bs[KC][BN + PAD];
    __shared__ float colred[16][BN];
    int tid = threadIdx.x;
    int tx = tid & 15, ty = tid >> 4;
    float acc[8][8];
#pragma unroll
    for (int i = 0; i < 8; i++)
#pragma unroll
        for (int j = 0; j < 8; j++) acc[i][j] = 0.f;

    const float* wm = w0 + 2 * Dd;
    const float* Ap = ctx + ((size_t)b * LC + cblk) * Dd;
    const float* Bp = qry + ((size_t)b * LQ + qblk) * Dd;

    for (int k0 = 0; k0 < Dd; k0 += KC) {
#pragma unroll
        for (int r = 0; r < 4; r++) {
            int u = tid + 256 * r;          // 1024 float4 slots per matrix
            int row = u >> 3;
            int kq = (u & 7) * 4;
            float4 v = *(const float4*)(Ap + (size_t)row * Dd + k0 + kq);
            float4 w = *(const float4*)(wm + k0 + kq);
            As[kq + 0][row] = v.x * w.x; As[kq + 1][row] = v.y * w.y;
            As[kq + 2][row] = v.z * w.z; As[kq + 3][row] = v.w * w.w;
            float4 q4 = *(const float4*)(Bp + (size_t)row * Dd + k0 + kq);
            Bs[kq + 0][row] = q4.x; Bs[kq + 1][row] = q4.y;
            Bs[kq + 2][row] = q4.z; Bs[kq + 3][row] = q4.w;
        }
        __syncthreads();
#pragma unroll 4
        for (int kk = 0; kk < KC; kk++) {
            float a[8], bv[8];
            *(float4*)&a[0] = *(const float4*)&As[kk][ty * 8];
            *(float4*)&a[4] = *(const float4*)&As[kk][ty * 8 + 4];
            *(float4*)&bv[0] = *(const float4*)&Bs[kk][tx * 8];
            *(float4*)&bv[4] = *(const float4*)&Bs[kk][tx * 8 + 4];
#pragma unroll
            for (int i = 0; i < 8; i++)
#pragma unroll
                for (int j = 0; j < 8; j++) acc[i][j] += a[i] * bv[j];
        }
        __syncthreads();
    }

    // epilogue: sim = acc + sc + sq; mask; E = exp(sim)
    float sqv[8];
    int qmv[8];
#pragma unroll
    for (int j = 0; j < 8; j++) {
        int q = qblk + tx * 8 + j;
        sqv[j] = g_sq[b * LQ + q];
        qmv[j] = g_qm[b * LQ + q];
    }
    float colpart[8];
#pragma unroll
    for (int j = 0; j < 8; j++) colpart[j] = 0.f;

#pragma unroll
    for (int i = 0; i < 8; i++) {
        int c = cblk + ty * 8 + i;
        float scv = g_sc[b * LC + c];
        int cmv = g_cm[b * LC + c];
        float e[8];
        float rowp = 0.f;
#pragma unroll
        for (int j = 0; j < 8; j++) {
            float s = acc[i][j] + scv + sqv[j];
            float ev = (cmv | qmv[j]) ? 0.f : __expf(s);
            e[j] = ev;
            rowp += ev;
            colpart[j] += ev;
        }
        float* ep = g_E + ((size_t)(b * LC + c)) * LQ + qblk + tx * 8;
        *(float4*)ep       = make_float4(e[0], e[1], e[2], e[3]);
        *(float4*)(ep + 4) = make_float4(e[4], e[5], e[6], e[7]);
        // reduce over the 16 tx-lanes (same ty => same 16-lane segment)
#pragma unroll
        for (int o = 8; o; o >>= 1) rowp += __shfl_xor_sync(0xffffffffu, rowp, o, 16);
        if (tx == 0) g_rowsum_part[((size_t)b * 2 + blockIdx.y) * LC + c] = rowp;
    }
#pragma unroll
    for (int j = 0; j < 8; j++) colred[ty][tx * 8 + j] = colpart[j];
    __syncthreads();
    if (tid < BN) {
        float s = 0.f;
#pragma unroll
        for (int t = 0; t < 16; t++) s += colred[t][tid];
        g_colsum_part[((size_t)b * 16 + blockIdx.x) * LQ + qblk + tid] = s;
    }
}

// ---------------- K2: deterministic partial reductions ----------------
__global__ void k2_reduce() {
    int b = blockIdx.x, tid = threadIdx.x;  // 256 threads
    for (int c = tid; c < LC; c += 256) {
        g_rowsum[b * LC + c] = g_rowsum_part[((size_t)b * 2 + 0) * LC + c] +
                               g_rowsum_part[((size_t)b * 2 + 1) * LC + c];
    }
    {
        int q = tid;
        float s = 0.f;
#pragma unroll
        for (int t = 0; t < 16; t++) s += g_colsum_part[((size_t)b * 16 + t) * LQ + q];
        g_colsum[b * LQ + q] = s;
    }
    {
        int d = tid;
        float s = 0.f;
#pragma unroll
        for (int t = 0; t < 8; t++) s += g_cmean_part[((size_t)b * 8 + t) * Dd + d];
        g_cmean[b * Dd + d] = s * (1.0f / LC);
    }
}

// ---------------- K3: T[q][d] = (1/colsum) * sum_c E[c][q]*ctx[c][d] (fallback cmean) -----
__global__ __launch_bounds__(256)
void k3_T(const float* __restrict__ ctx) {
    int b = blockIdx.z;
    int qblk = blockIdx.x * BM;  // 2 tiles
    int dblk = blockIdx.y * BN;  // 2 tiles
    __shared__ float As[KC][BM + PAD];
    __shared__ float Bs[KC][BN + PAD];
    int tid = threadIdx.x, tx = tid & 15, ty = tid >> 4;
    float acc[8][8];
#pragma unroll
    for (int i = 0; i < 8; i++)
#pragma unroll
        for (int j = 0; j < 8; j++) acc[i][j] = 0.f;

    const float* Ep = g_E + (size_t)b * LC * LQ;
    const float* Cp = ctx + (size_t)b * LC * Dd;

    for (int k0 = 0; k0 < LC; k0 += KC) {
#pragma unroll
        for (int r = 0; r < 4; r++) {
            int u = tid + 256 * r;
            int kk = u >> 5;
            int m4 = (u & 31) * 4;
            *(float4*)&As[kk][m4] = *(const float4*)(Ep + (size_t)(k0 + kk) * LQ + qblk + m4);
            *(float4*)&Bs[kk][m4] = *(const float4*)(Cp + (size_t)(k0 + kk) * Dd + dblk + m4);
        }
        __syncthreads();
#pragma unroll 4
        for (int kk = 0; kk < KC; kk++) {
            float a[8], bv[8];
            *(float4*)&a[0] = *(const float4*)&As[kk][ty * 8];
            *(float4*)&a[4] = *(const float4*)&As[kk][ty * 8 + 4];
            *(float4*)&bv[0] = *(const float4*)&Bs[kk][tx * 8];
            *(float4*)&bv[4] = *(const float4*)&Bs[kk][tx * 8 + 4];
#pragma unroll
            for (int i = 0; i < 8; i++)
#pragma unroll
                for (int j = 0; j < 8; j++) acc[i][j] += a[i] * bv[j];
        }
        __syncthreads();
    }

#pragma unroll
    for (int i = 0; i < 8; i++) {
        int q = qblk + ty * 8 + i;
        float cs = g_colsum[b * LQ + q];
        float* Tp = g_T + ((size_t)b * LQ + q) * Dd + dblk + tx * 8;
        if (cs > 0.f) {
            float inv = 1.0f / cs;
            *(float4*)Tp = make_float4(acc[i][0] * inv, acc[i][1] * inv,
                                       acc[i][2] * inv, acc[i][3] * inv);
            *(float4*)(Tp + 4) = make_float4(acc[i][4] * inv, acc[i][5] * inv,
                                             acc[i][6] * inv, acc[i][7] * inv);
        } else {
            const float* fb = g_cmean + b * Dd + dblk + tx * 8;
            *(float4*)Tp = make_float4(fb[0], fb[1], fb[2], fb[3]);
            *(float4*)(Tp + 4) = make_float4(fb[4], fb[5], fb[6], fb[7]);
        }
    }
}

// ---------------- K3b: tmean = mean_q T ----------------
__global__ void k3b_tmean() {
    int b = blockIdx.x, d = threadIdx.x;  // 256 threads
    const float* p = g_T + (size_t)b * LQ * Dd + d;
    float s0 = 0, s1 = 0, s2 = 0, s3 = 0;
    for (int q = 0; q < LQ; q += 4) {
        s0 += p[(size_t)(q + 0) * Dd]; s1 += p[(size_t)(q + 1) * Dd];
        s2 += p[(size_t)(q + 2) * Dd]; s3 += p[(size_t)(q + 3) * Dd];
    }
    g_tmean[b * Dd + d] = ((s0 + s1) + (s2 + s3)) * (1.0f / LQ);
}

// ---------------- K4: A = E@query / rowsum ; Bmat = E@T / rowsum (uniform fallbacks) -----
__global__ __launch_bounds__(256)
void k4_out(const float* __restrict__ qry, float* __restrict__ out) {
    int b = blockIdx.z;
    int cblk = blockIdx.x * BM;              // 16 tiles
    int sel = blockIdx.y >> 1;               // 0 = A, 1 = Bmat
    int dblk = (blockIdx.y & 1) * BN;        // 2 tiles
    const float* Bsrc = sel ? (g_T + (size_t)b * LQ * Dd) : (qry + (size_t)b * LQ * Dd);
    const float* fb = (sel ? g_tmean : g_qmean) + b * Dd;
    float* op = out + (size_t)sel * Bb * LC * Dd + (size_t)b * LC * Dd;

    __shared__ float As[KC][BM + PAD];
    __shared__ float Bs[KC][BN + PAD];
    int tid = threadIdx.x, tx = tid & 15, ty = tid >> 4;
    float acc[8][8];
#pragma unroll
    for (int i = 0; i < 8; i++)
#pragma unroll
        for (int j = 0; j < 8; j++) acc[i][j] = 0.f;

    const float* Ep = g_E + ((size_t)b * LC + cblk) * LQ;

    for (int k0 = 0; k0 < LQ; k0 += KC) {
#pragma unroll
        for (int r = 0; r < 4; r++) {
            int u = tid + 256 * r;
            // A tile: E rows (k = q contiguous) -> transpose into As[k][m]
            int row = u >> 3;
            int kq = (u & 7) * 4;
            float4 v = *(const float4*)(Ep + (size_t)row * LQ + k0 + kq);
            As[kq + 0][row] = v.x; As[kq + 1][row] = v.y;
            As[kq + 2][row] = v.z; As[kq + 3][row] = v.w;
            // B tile: Bsrc[k=q][n=d] directly
            int kk = u >> 5;
            int m4 = (u & 31) * 4;
            *(float4*)&Bs[kk][m4] = *(const float4*)(Bsrc + (size_t)(k0 + kk) * Dd + dblk + m4);
        }
        __syncthreads();
#pragma unroll 4
        for (int kk = 0; kk < KC; kk++) {
            float a[8], bv[8];
            *(float4*)&a[0] = *(const float4*)&As[kk][ty * 8];
            *(float4*)&a[4] = *(const float4*)&As[kk][ty * 8 + 4];
            *(float4*)&bv[0] = *(const float4*)&Bs[kk][tx * 8];
            *(float4*)&bv[4] = *(const float4*)&Bs[kk][tx * 8 + 4];
#pragma unroll
            for (int i = 0; i < 8; i++)
#pragma unroll
                for (int j = 0; j < 8; j++) acc[i][j] += a[i] * bv[j];
        }
        __syncthreads();
    }

#pragma unroll
    for (int i = 0; i < 8; i++) {
        int c = cblk + ty * 8 + i;
        float rs = g_rowsum[b * LC + c];
        float* dst = op + (size_t)c * Dd + dblk + tx * 8;
        if (rs > 0.f) {
            float inv = 1.0f / rs;
            *(float4*)dst = make_float4(acc[i][0] * inv, acc[i][1] * inv,
                                        acc[i][2] * inv, acc[i][3] * inv);
            *(float4*)(dst + 4) = make_float4(acc[i][4] * inv, acc[i][5] * inv,
                                              acc[i][6] * inv, acc[i][7] * inv);
        } else {
            const float* f = fb + dblk + tx * 8;
            *(float4*)dst = make_float4(f[0], f[1], f[2], f[3]);
            *(float4*)(dst + 4) = make_float4(f[4], f[5], f[6], f[7]);
        }
    }
}

// ---------------- launcher ----------------
extern "C" void kernel_launch(void* const* d_in, const int* in_sizes, int n_in,
                              void* d_out, int out_size) {
    const float* ctx = (const float*)d_in[0];
    const float* qry = (const float*)d_in[1];
    const void* cmask = d_in[2];
    const void* qmask = d_in[3];
    const float* w0 = (const float*)d_in[4];
    float* out = (float*)d_out;

    k_detect<<<1, 32>>>((const unsigned char*)cmask);
    k_cvt_mask<<<(Bb * LC + 255) / 256, 256>>>(cmask, qmask);
    k0_rowdots<<<(Bb * (LC + LQ)) / 8, 256>>>(ctx, qry, w0);
    k0_means<<<dim3(Bb, 9), 256>>>(ctx, qry);
    k1_exp<<<dim3(LC / BM, LQ / BN, Bb), 256>>>(ctx, qry, w0);
    k2_reduce<<<Bb, 256>>>();
    k3_T<<<dim3(LQ / BM, Dd / BN, Bb), 256>>>(ctx);
    k3b_tmean<<<Bb, 256>>>();
    k4_out<<<dim3(LC / BM, 4, Bb), 256>>>(qry, out);
}

// round 11
// speedup vs baseline: 1.0004x; 1.0004x over previous
#include <cuda_runtime.h>
#include <math.h>

// Problem dims
#define Bb 32
#define LC 2048
#define LQ 256
#define Dd 256

// GEMM tiling
#define BM 128
#define BN 128
#define KC 32
#define PAD 4

// ---------------- scratch (device globals; no allocations allowed) ----------------
__device__ float g_E[(size_t)Bb * LC * LQ];          // exp(sim), 0 at masked  (67 MB)
__device__ float g_T[(size_t)Bb * LQ * Dd];          // T = SS^T @ context      (8 MB)
__device__ float g_sc[Bb * LC];
__device__ float g_sq[Bb * LQ];
__device__ float g_rowsum_part[Bb * 2 * LC];         // per q-tile partials
__device__ float g_rowsum[Bb * LC];
__device__ float g_colsum_part[Bb * 16 * LQ];        // per c-tile partials
__device__ float g_colsum[Bb * LQ];
__device__ float g_qmean[Bb * Dd];
__device__ float g_cmean_part[Bb * 8 * Dd];
__device__ float g_cmean[Bb * Dd];
__device__ float g_tmean[Bb * Dd];
__device__ unsigned char g_cm[Bb * LC];
__device__ unsigned char g_qm[Bb * LQ];
__device__ int g_is32;

// ---------------- mask dtype detection + canonicalization ----------------
// numpy bool -> 1 byte/elem (random 0/1 bytes). If harness widened to int32,
// every element is {v,0,0,0} little-endian -> bytes at (i%4!=0) are all zero.
__global__ void k_detect(const unsigned char* __restrict__ cm) {
    if (threadIdx.x == 0 && blockIdx.x == 0) {
        int is32 = 1;
        for (int i = 0; i < 4096; i++) {
            if ((i & 3) && cm[i]) { is32 = 0; break; }
        }
        g_is32 = is32;
    }
}

__global__ void k_cvt_mask(const void* __restrict__ cm, const void* __restrict__ qm) {
    int i = blockIdx.x * 256 + threadIdx.x;
    int is32 = g_is32;
    if (i < Bb * LC) {
        g_cm[i] = is32 ? (unsigned char)(((const int*)cm)[i] != 0)
                       : (unsigned char)(((const unsigned char*)cm)[i] != 0);
    }
    if (i < Bb * LQ) {
        g_qm[i] = is32 ? (unsigned char)(((const int*)qm)[i] != 0)
                       : (unsigned char)(((const unsigned char*)qm)[i] != 0);
    }
}

// ---------------- K0a: sc = context @ wc, sq = query @ wq ----------------
__global__ void k0_rowdots(const float* __restrict__ ctx, const float* __restrict__ qry,
                           const float* __restrict__ w0) {
    int warp = (blockIdx.x * blockDim.x + threadIdx.x) >> 5;
    int lane = threadIdx.x & 31;
    const int nC = Bb * LC;
    const float* src;
    const float* wgt;
    float* dst;
    if (warp < nC) {
        src = ctx + (size_t)warp * Dd; wgt = w0; dst = g_sc + warp;
    } else {
        int r = warp - nC;
        if (r >= Bb * LQ) return;
        src = qry + (size_t)r * Dd; wgt = w0 + Dd; dst = g_sq + r;
    }
    float s = 0.f;
#pragma unroll
    for (int i = 0; i < 2; i++) {
        int idx = (lane + 32 * i) * 4;
        float4 v = *(const float4*)(src + idx);
        float4 w = *(const float4*)(wgt + idx);
        s += v.x * w.x + v.y * w.y + v.z * w.z + v.w * w.w;
    }
#pragma unroll
    for (int o = 16; o; o >>= 1) s += __shfl_xor_sync(0xffffffffu, s, o);
    if (lane == 0) *dst = s;
}

// ---------------- K0b: qmean, cmean partials ----------------
__global__ void k0_means(const float* __restrict__ ctx, const float* __restrict__ qry) {
    int b = blockIdx.x, y = blockIdx.y, d = threadIdx.x;  // 256 threads = D
    if (y == 0) {
        const float* p = qry + (size_t)b * LQ * Dd + d;
        float s0 = 0, s1 = 0, s2 = 0, s3 = 0, s4 = 0, s5 = 0, s6 = 0, s7 = 0;
        for (int q = 0; q < LQ; q += 8) {
            s0 += p[(size_t)(q + 0) * Dd]; s1 += p[(size_t)(q + 1) * Dd];
            s2 += p[(size_t)(q + 2) * Dd]; s3 += p[(size_t)(q + 3) * Dd];
            s4 += p[(size_t)(q + 4) * Dd]; s5 += p[(size_t)(q + 5) * Dd];
            s6 += p[(size_t)(q + 6) * Dd]; s7 += p[(size_t)(q + 7) * Dd];
        }
        g_qmean[b * Dd + d] = (((s0 + s1) + (s2 + s3)) + ((s4 + s5) + (s6 + s7))) * (1.0f / LQ);
    } else {
        int chunk = y - 1;  // 8 chunks of 256 context rows
        const float* p = ctx + ((size_t)b * LC + chunk * 256) * Dd + d;
        float s0 = 0, s1 = 0, s2 = 0, s3 = 0, s4 = 0, s5 = 0, s6 = 0, s7 = 0;
        for (int c = 0; c < 256; c += 8) {
            s0 += p[(size_t)(c + 0) * Dd]; s1 += p[(size_t)(c + 1) * Dd];
            s2 += p[(size_t)(c + 2) * Dd]; s3 += p[(size_t)(c + 3) * Dd];
            s4 += p[(size_t)(c + 4) * Dd]; s5 += p[(size_t)(c + 5) * Dd];
            s6 += p[(size_t)(c + 6) * Dd]; s7 += p[(size_t)(c + 7) * Dd];
        }
        g_cmean_part[((size_t)b * 8 + chunk) * Dd + d] =
            ((s0 + s1) + (s2 + s3)) + ((s4 + s5) + (s6 + s7));
    }
}

// ---------------- K1: E = exp(sim) (masked -> 0) + row/col partial sums ----------------
__global__ __launch_bounds__(256)
void k1_exp(const float* __restrict__ ctx, const float* __restrict__ qry,
            const float* __restrict__ w0) {
    int b = blockIdx.z;
    int cblk = blockIdx.x * BM;   // 16 tiles
    int qblk = blockIdx.y * BN;   // 2 tiles
    __shared__ float As[KC][BM + PAD];
    __shared__ float Bs[KC][BN + PAD];
    __shared__ float colred[16][BN];
    int tid = threadIdx.x;
    int tx = tid & 15, ty = tid >> 4;
    float acc[8][8];
#pragma unroll
    for (int i = 0; i < 8; i++)
#pragma unroll
        for (int j = 0; j < 8; j++) acc[i][j] = 0.f;

    const float* wm = w0 + 2 * Dd;
    const float* Ap = ctx + ((size_t)b * LC + cblk) * Dd;
    const float* Bp = qry + ((size_t)b * LQ + qblk) * Dd;

    for (int k0 = 0; k0 < Dd; k0 += KC) {
#pragma unroll
        for (int r = 0; r < 4; r++) {
            int u = tid + 256 * r;          // 1024 float4 slots per matrix
            int row = u >> 3;
            int kq = (u & 7) * 4;
            float4 v = *(const float4*)(Ap + (size_t)row * Dd + k0 + kq);
            float4 w = *(const float4*)(wm + k0 + kq);
            As[kq + 0][row] = v.x * w.x; As[kq + 1][row] = v.y * w.y;
            As[kq + 2][row] = v.z * w.z; As[kq + 3][row] = v.w * w.w;
            float4 q4 = *(const float4*)(Bp + (size_t)row * Dd + k0 + kq);
            Bs[kq + 0][row] = q4.x; Bs[kq + 1][row] = q4.y;
            Bs[kq + 2][row] = q4.z; Bs[kq + 3][row] = q4.w;
        }
        __syncthreads();
#pragma unroll 4
        for (int kk = 0; kk < KC; kk++) {
            float a[8], bv[8];
            *(float4*)&a[0] = *(const float4*)&As[kk][ty * 8];
            *(float4*)&a[4] = *(const float4*)&As[kk][ty * 8 + 4];
            *(float4*)&bv[0] = *(const float4*)&Bs[kk][tx * 8];
            *(float4*)&bv[4] = *(const float4*)&Bs[kk][tx * 8 + 4];
#pragma unroll
            for (int i = 0; i < 8; i++)
#pragma unroll
                for (int j = 0; j < 8; j++) acc[i][j] += a[i] * bv[j];
        }
        __syncthreads();
    }

    // epilogue: sim = acc + sc + sq; mask; E = exp(sim)
    float sqv[8];
    int qmv[8];
#pragma unroll
    for (int j = 0; j < 8; j++) {
        int q = qblk + tx * 8 + j;
        sqv[j] = g_sq[b * LQ + q];
        qmv[j] = g_qm[b * LQ + q];
    }
    float colpart[8];
#pragma unroll
    for (int j = 0; j < 8; j++) colpart[j] = 0.f;

#pragma unroll
    for (int i = 0; i < 8; i++) {
        int c = cblk + ty * 8 + i;
        float scv = g_sc[b * LC + c];
        int cmv = g_cm[b * LC + c];
        float e[8];
        float rowp = 0.f;
#pragma unroll
        for (int j = 0; j < 8; j++) {
            float s = acc[i][j] + scv + sqv[j];
            float ev = (cmv | qmv[j]) ? 0.f : __expf(s);
            e[j] = ev;
            rowp += ev;
            colpart[j] += ev;
        }
        float* ep = g_E + ((size_t)(b * LC + c)) * LQ + qblk + tx * 8;
        *(float4*)ep       = make_float4(e[0], e[1], e[2], e[3]);
        *(float4*)(ep + 4) = make_float4(e[4], e[5], e[6], e[7]);
        // reduce over the 16 tx-lanes (same ty => same 16-lane segment)
#pragma unroll
        for (int o = 8; o; o >>= 1) rowp += __shfl_xor_sync(0xffffffffu, rowp, o, 16);
        if (tx == 0) g_rowsum_part[((size_t)b * 2 + blockIdx.y) * LC + c] = rowp;
    }
#pragma unroll
    for (int j = 0; j < 8; j++) colred[ty][tx * 8 + j] = colpart[j];
    __syncthreads();
    if (tid < BN) {
        float s = 0.f;
#pragma unroll
        for (int t = 0; t < 16; t++) s += colred[t][tid];
        g_colsum_part[((size_t)b * 16 + blockIdx.x) * LQ + qblk + tid] = s;
    }
}

// ---------------- K2: deterministic partial reductions ----------------
__global__ void k2_reduce() {
    int b = blockIdx.x, tid = threadIdx.x;  // 256 threads
    for (int c = tid; c < LC; c += 256) {
        g_rowsum[b * LC + c] = g_rowsum_part[((size_t)b * 2 + 0) * LC + c] +
                               g_rowsum_part[((size_t)b * 2 + 1) * LC + c];
    }
    {
        int q = tid;
        float s = 0.f;
#pragma unroll
        for (int t = 0; t < 16; t++) s += g_colsum_part[((size_t)b * 16 + t) * LQ + q];
        g_colsum[b * LQ + q] = s;
    }
    {
        int d = tid;
        float s = 0.f;
#pragma unroll
        for (int t = 0; t < 8; t++) s += g_cmean_part[((size_t)b * 8 + t) * Dd + d];
        g_cmean[b * Dd + d] = s * (1.0f / LC);
    }
}

// ---------------- K3: T[q][d] = (1/colsum) * sum_c E[c][q]*ctx[c][d] (fallback cmean) -----
__global__ __launch_bounds__(256)
void k3_T(const float* __restrict__ ctx) {
    int b = blockIdx.z;
    int qblk = blockIdx.x * BM;  // 2 tiles
    int dblk = blockIdx.y * BN;  // 2 tiles
    __shared__ float As[KC][BM + PAD];
    __shared__ float Bs[KC][BN + PAD];
    int tid = threadIdx.x, tx = tid & 15, ty = tid >> 4;
    float acc[8][8];
#pragma unroll
    for (int i = 0; i < 8; i++)
#pragma unroll
        for (int j = 0; j < 8; j++) acc[i][j] = 0.f;

    const float* Ep = g_E + (size_t)b * LC * LQ;
    const float* Cp = ctx + (size_t)b * LC * Dd;

    for (int k0 = 0; k0 < LC; k0 += KC) {
#pragma unroll
        for (int r = 0; r < 4; r++) {
            int u = tid + 256 * r;
            int kk = u >> 5;
            int m4 = (u & 31) * 4;
            *(float4*)&As[kk][m4] = *(const float4*)(Ep + (size_t)(k0 + kk) * LQ + qblk + m4);
            *(float4*)&Bs[kk][m4] = *(const float4*)(Cp + (size_t)(k0 + kk) * Dd + dblk + m4);
        }
        __syncthreads();
#pragma unroll 4
        for (int kk = 0; kk < KC; kk++) {
            float a[8], bv[8];
            *(float4*)&a[0] = *(const float4*)&As[kk][ty * 8];
            *(float4*)&a[4] = *(const float4*)&As[kk][ty * 8 + 4];
            *(float4*)&bv[0] = *(const float4*)&Bs[kk][tx * 8];
            *(float4*)&bv[4] = *(const float4*)&Bs[kk][tx * 8 + 4];
#pragma unroll
            for (int i = 0; i < 8; i++)
#pragma unroll
                for (int j = 0; j < 8; j++) acc[i][j] += a[i] * bv[j];
        }
        __syncthreads();
    }

#pragma unroll
    for (int i = 0; i < 8; i++) {
        int q = qblk + ty * 8 + i;
        float cs = g_colsum[b * LQ + q];
        float* Tp = g_T + ((size_t)b * LQ + q) * Dd + dblk + tx * 8;
        if (cs > 0.f) {
            float inv = 1.0f / cs;
            *(float4*)Tp = make_float4(acc[i][0] * inv, acc[i][1] * inv,
                                       acc[i][2] * inv, acc[i][3] * inv);
            *(float4*)(Tp + 4) = make_float4(acc[i][4] * inv, acc[i][5] * inv,
                                             acc[i][6] * inv, acc[i][7] * inv);
        } else {
            const float* fb = g_cmean + b * Dd + dblk + tx * 8;
            *(float4*)Tp = make_float4(fb[0], fb[1], fb[2], fb[3]);
            *(float4*)(Tp + 4) = make_float4(fb[4], fb[5], fb[6], fb[7]);
        }
    }
}

// ---------------- K3b: tmean = mean_q T ----------------
__global__ void k3b_tmean() {
    int b = blockIdx.x, d = threadIdx.x;  // 256 threads
    const float* p = g_T + (size_t)b * LQ * Dd + d;
    float s0 = 0, s1 = 0, s2 = 0, s3 = 0;
    for (int q = 0; q < LQ; q += 4) {
        s0 += p[(size_t)(q + 0) * Dd]; s1 += p[(size_t)(q + 1) * Dd];
        s2 += p[(size_t)(q + 2) * Dd]; s3 += p[(size_t)(q + 3) * Dd];
    }
    g_tmean[b * Dd + d] = ((s0 + s1) + (s2 + s3)) * (1.0f / LQ);
}

// ---------------- K4: A = E@query / rowsum ; Bmat = E@T / rowsum (uniform fallbacks) -----
__global__ __launch_bounds__(256)
void k4_out(const float* __restrict__ qry, float* __restrict__ out) {
    int b = blockIdx.z;
    int cblk = blockIdx.x * BM;              // 16 tiles
    int sel = blockIdx.y >> 1;               // 0 = A, 1 = Bmat
    int dblk = (blockIdx.y & 1) * BN;        // 2 tiles
    const float* Bsrc = sel ? (g_T + (size_t)b * LQ * Dd) : (qry + (size_t)b * LQ * Dd);
    const float* fb = (sel ? g_tmean : g_qmean) + b * Dd;
    float* op = out + (size_t)sel * Bb * LC * Dd + (size_t)b * LC * Dd;

    __shared__ float As[KC][BM + PAD];
    __shared__ float Bs[KC][BN + PAD];
    int tid = threadIdx.x, tx = tid & 15, ty = tid >> 4;
    float acc[8][8];
#pragma unroll
    for (int i = 0; i < 8; i++)
#pragma unroll
        for (int j = 0; j < 8; j++) acc[i][j] = 0.f;

    const float* Ep = g_E + ((size_t)b * LC + cblk) * LQ;

    for (int k0 = 0; k0 < LQ; k0 += KC) {
#pragma unroll
        for (int r = 0; r < 4; r++) {
            int u = tid + 256 * r;
            // A tile: E rows (k = q contiguous) -> transpose into As[k][m]
            int row = u >> 3;
            int kq = (u & 7) * 4;
            float4 v = *(const float4*)(Ep + (size_t)row * LQ + k0 + kq);
            As[kq + 0][row] = v.x; As[kq + 1][row] = v.y;
            As[kq + 2][row] = v.z; As[kq + 3][row] = v.w;
            // B tile: Bsrc[k=q][n=d] directly
            int kk = u >> 5;
            int m4 = (u & 31) * 4;
            *(float4*)&Bs[kk][m4] = *(const float4*)(Bsrc + (size_t)(k0 + kk) * Dd + dblk + m4);
        }
        __syncthreads();
#pragma unroll 4
        for (int kk = 0; kk < KC; kk++) {
            float a[8], bv[8];
            *(float4*)&a[0] = *(const float4*)&As[kk][ty * 8];
            *(float4*)&a[4] = *(const float4*)&As[kk][ty * 8 + 4];
            *(float4*)&bv[0] = *(const float4*)&Bs[kk][tx * 8];
            *(float4*)&bv[4] = *(const float4*)&Bs[kk][tx * 8 + 4];
#pragma unroll
            for (int i = 0; i < 8; i++)
#pragma unroll
                for (int j = 0; j < 8; j++) acc[i][j] += a[i] * bv[j];
        }
        __syncthreads();
    }

#pragma unroll
    for (int i = 0; i < 8; i++) {
        int c = cblk + ty * 8 + i;
        float rs = g_rowsum[b * LC + c];
        float* dst = op + (size_t)c * Dd + dblk + tx * 8;
        if (rs > 0.f) {
            float inv = 1.0f / rs;
            *(float4*)dst = make_float4(acc[i][0] * inv, acc[i][1] * inv,
                                        acc[i][2] * inv, acc[i][3] * inv);
            *(float4*)(dst + 4) = make_float4(acc[i][4] * inv, acc[i][5] * inv,
                                              acc[i][6] * inv, acc[i][7] * inv);
        } else {
            const float* f = fb + dblk + tx * 8;
            *(float4*)dst = make_float4(f[0], f[1], f[2], f[3]);
            *(float4*)(dst + 4) = make_float4(f[4], f[5], f[6], f[7]);
        }
    }
}

// ---------------- launcher ----------------
extern "C" void kernel_launch(void* const* d_in, const int* in_sizes, int n_in,
                              void* d_out, int out_size) {
    const float* ctx = (const float*)d_in[0];
    const float* qry = (const float*)d_in[1];
    const void* cmask = d_in[2];
    const void* qmask = d_in[3];
    const float* w0 = (const float*)d_in[4];
    float* out = (float*)d_out;

    k_detect<<<1, 32>>>((const unsigned char*)cmask);
    k_cvt_mask<<<(Bb * LC + 255) / 256, 256>>>(cmask, qmask);
    k0_rowdots<<<(Bb * (LC + LQ)) / 8, 256>>>(ctx, qry, w0);
    k0_means<<<dim3(Bb, 9), 256>>>(ctx, qry);
    k1_exp<<<dim3(LC / BM, LQ / BN, Bb), 256>>>(ctx, qry, w0);
    k2_reduce<<<Bb, 256>>>();
    k3_T<<<dim3(LQ / BM, Dd / BN, Bb), 256>>>(ctx);
    k3b_tmean<<<Bb, 256>>>();
    k4_out<<<dim3(LC / BM, 4, Bb), 256>>>(qry, out);
}

// round 12
// speedup vs baseline: 1.1457x; 1.1452x over previous
#include <cuda_runtime.h>
#include <math.h>

// Problem dims
#define Bb 32
#define LC 2048
#define LQ 256
#define Dd 256

// GEMM tiling
#define BM 128
#define BN 128
#define KC 32
#define PAD 4   // keeps rows 16B-aligned: (BM+PAD)*4 = 528 bytes

// ---------------- packed f32x2 helpers (FFMA2 path; ptxas never emits these from C++) ----
__device__ __forceinline__ unsigned long long dupf2(float x) {
    unsigned long long r;
    asm("mov.b64 %0, {%1, %1};" : "=l"(r) : "f"(x));
    return r;
}
__device__ __forceinline__ void fma2(unsigned long long& d, unsigned long long a,
                                     unsigned long long b) {
    asm("fma.rn.f32x2 %0, %1, %2, %0;" : "+l"(d) : "l"(a), "l"(b));
}
__device__ __forceinline__ float2 unpk(unsigned long long v) {
    float2 f;
    asm("mov.b64 {%0, %1}, %2;" : "=f"(f.x), "=f"(f.y) : "l"(v));
    return f;
}

// ---------------- scratch (device globals; no allocations allowed) ----------------
__device__ float g_E[(size_t)Bb * LC * LQ];          // exp(sim), 0 at masked  (67 MB)
__device__ float g_T[(size_t)Bb * LQ * Dd];          // T = SS^T @ context      (8 MB)
__device__ float g_sc[Bb * LC];
__device__ float g_sq[Bb * LQ];
__device__ float g_rowsum_part[Bb * 2 * LC];         // per q-tile partials
__device__ float g_rowsum[Bb * LC];
__device__ float g_colsum_part[Bb * 16 * LQ];        // per c-tile partials
__device__ float g_colsum[Bb * LQ];
__device__ float g_qmean[Bb * Dd];
__device__ float g_cmean_part[Bb * 8 * Dd];
__device__ float g_cmean[Bb * Dd];
__device__ float g_tmean[Bb * Dd];
__device__ unsigned char g_cm[Bb * LC];
__device__ unsigned char g_qm[Bb * LQ];
__device__ int g_is32;

// ---------------- mask dtype detection + canonicalization ----------------
__global__ void k_detect(const unsigned char* __restrict__ cm) {
    if (threadIdx.x == 0 && blockIdx.x == 0) {
        int is32 = 1;
        for (int i = 0; i < 4096; i++) {
            if ((i & 3) && cm[i]) { is32 = 0; break; }
        }
        g_is32 = is32;
    }
}

__global__ void k_cvt_mask(const void* __restrict__ cm, const void* __restrict__ qm) {
    int i = blockIdx.x * 256 + threadIdx.x;
    int is32 = g_is32;
    if (i < Bb * LC) {
        g_cm[i] = is32 ? (unsigned char)(((const int*)cm)[i] != 0)
                       : (unsigned char)(((const unsigned char*)cm)[i] != 0);
    }
    if (i < Bb * LQ) {
        g_qm[i] = is32 ? (unsigned char)(((const int*)qm)[i] != 0)
                       : (unsigned char)(((const unsigned char*)qm)[i] != 0);
    }
}

// ---------------- K0a: sc = context @ wc, sq = query @ wq ----------------
__global__ void k0_rowdots(const float* __restrict__ ctx, const float* __restrict__ qry,
                           const float* __restrict__ w0) {
    int warp = (blockIdx.x * blockDim.x + threadIdx.x) >> 5;
    int lane = threadIdx.x & 31;
    const int nC = Bb * LC;
    const float* src;
    const float* wgt;
    float* dst;
    if (warp < nC) {
        src = ctx + (size_t)warp * Dd; wgt = w0; dst = g_sc + warp;
    } else {
        int r = warp - nC;
        if (r >= Bb * LQ) return;
        src = qry + (size_t)r * Dd; wgt = w0 + Dd; dst = g_sq + r;
    }
    float s = 0.f;
#pragma unroll
    for (int i = 0; i < 2; i++) {
        int idx = (lane + 32 * i) * 4;
        float4 v = *(const float4*)(src + idx);
        float4 w = *(const float4*)(wgt + idx);
        s += v.x * w.x + v.y * w.y + v.z * w.z + v.w * w.w;
    }
#pragma unroll
    for (int o = 16; o; o >>= 1) s += __shfl_xor_sync(0xffffffffu, s, o);
    if (lane == 0) *dst = s;
}

// ---------------- K0b: qmean, cmean partials ----------------
__global__ void k0_means(const float* __restrict__ ctx, const float* __restrict__ qry) {
    int b = blockIdx.x, y = blockIdx.y, d = threadIdx.x;  // 256 threads = D
    if (y == 0) {
        const float* p = qry + (size_t)b * LQ * Dd + d;
        float s0 = 0, s1 = 0, s2 = 0, s3 = 0, s4 = 0, s5 = 0, s6 = 0, s7 = 0;
        for (int q = 0; q < LQ; q += 8) {
            s0 += p[(size_t)(q + 0) * Dd]; s1 += p[(size_t)(q + 1) * Dd];
            s2 += p[(size_t)(q + 2) * Dd]; s3 += p[(size_t)(q + 3) * Dd];
            s4 += p[(size_t)(q + 4) * Dd]; s5 += p[(size_t)(q + 5) * Dd];
            s6 += p[(size_t)(q + 6) * Dd]; s7 += p[(size_t)(q + 7) * Dd];
        }
        g_qmean[b * Dd + d] = (((s0 + s1) + (s2 + s3)) + ((s4 + s5) + (s6 + s7))) * (1.0f / LQ);
    } else {
        int chunk = y - 1;  // 8 chunks of 256 context rows
        const float* p = ctx + ((size_t)b * LC + chunk * 256) * Dd + d;
        float s0 = 0, s1 = 0, s2 = 0, s3 = 0, s4 = 0, s5 = 0, s6 = 0, s7 = 0;
        for (int c = 0; c < 256; c += 8) {
            s0 += p[(size_t)(c + 0) * Dd]; s1 += p[(size_t)(c + 1) * Dd];
            s2 += p[(size_t)(c + 2) * Dd]; s3 += p[(size_t)(c + 3) * Dd];
            s4 += p[(size_t)(c + 4) * Dd]; s5 += p[(size_t)(c + 5) * Dd];
            s6 += p[(size_t)(c + 6) * Dd]; s7 += p[(size_t)(c + 7) * Dd];
        }
        g_cmean_part[((size_t)b * 8 + chunk) * Dd + d] =
            ((s0 + s1) + (s2 + s3)) + ((s4 + s5) + (s6 + s7));
    }
}

// ---------------- shared FFMA2 micro-kernel body (8x8 tile as 8x4 f32x2 pairs) ----------
#define MICRO_FFMA2(As_, Bs_, acc2_)                                                   \
    _Pragma("unroll 4")                                                                \
    for (int kk = 0; kk < KC; kk++) {                                                  \
        float4 a0 = *(const float4*)&As_[kk][ty * 8];                                  \
        float4 a1 = *(const float4*)&As_[kk][ty * 8 + 4];                              \
        ulonglong2 b01 = *(const ulonglong2*)&Bs_[kk][tx * 8];                         \
        ulonglong2 b23 = *(const ulonglong2*)&Bs_[kk][tx * 8 + 4];                     \
        unsigned long long bb0 = b01.x, bb1 = b01.y, bb2 = b23.x, bb3 = b23.y;         \
        float av[8] = {a0.x, a0.y, a0.z, a0.w, a1.x, a1.y, a1.z, a1.w};                \
        _Pragma("unroll")                                                              \
        for (int i = 0; i < 8; i++) {                                                  \
            unsigned long long aa = dupf2(av[i]);                                      \
            fma2(acc2_[i][0], aa, bb0);                                                \
            fma2(acc2_[i][1], aa, bb1);                                                \
            fma2(acc2_[i][2], aa, bb2);                                                \
            fma2(acc2_[i][3], aa, bb3);                                                \
        }                                                                              \
    }

// ---------------- K1: E = exp(sim) (masked -> 0) + row/col partial sums ----------------
__global__ __launch_bounds__(256, 2)
void k1_exp(const float* __restrict__ ctx, const float* __restrict__ qry,
            const float* __restrict__ w0) {
    int b = blockIdx.z;
    int cblk = blockIdx.x * BM;   // 16 tiles
    int qblk = blockIdx.y * BN;   // 2 tiles
    __shared__ float As[KC][BM + PAD];
    __shared__ float Bs[KC][BN + PAD];
    __shared__ float colred[16][BN];
    int tid = threadIdx.x;
    int tx = tid & 15, ty = tid >> 4;
    unsigned long long acc2[8][4];
#pragma unroll
    for (int i = 0; i < 8; i++)
#pragma unroll
        for (int j = 0; j < 4; j++) acc2[i][j] = 0ull;

    const float* wm = w0 + 2 * Dd;
    const float* Ap = ctx + ((size_t)b * LC + cblk) * Dd;
    const float* Bp = qry + ((size_t)b * LQ + qblk) * Dd;

    for (int k0 = 0; k0 < Dd; k0 += KC) {
#pragma unroll
        for (int r = 0; r < 4; r++) {
            int u = tid + 256 * r;          // 1024 float4 slots per matrix
            int row = u >> 3;
            int kq = (u & 7) * 4;
            float4 v = *(const float4*)(Ap + (size_t)row * Dd + k0 + kq);
            float4 w = *(const float4*)(wm + k0 + kq);
            As[kq + 0][row] = v.x * w.x; As[kq + 1][row] = v.y * w.y;
            As[kq + 2][row] = v.z * w.z; As[kq + 3][row] = v.w * w.w;
            float4 q4 = *(const float4*)(Bp + (size_t)row * Dd + k0 + kq);
            Bs[kq + 0][row] = q4.x; Bs[kq + 1][row] = q4.y;
            Bs[kq + 2][row] = q4.z; Bs[kq + 3][row] = q4.w;
        }
        __syncthreads();
        MICRO_FFMA2(As, Bs, acc2)
        __syncthreads();
    }

    // epilogue: sim = acc + sc + sq; mask; E = exp(sim)
    float sqv[8];
    int qmv[8];
#pragma unroll
    for (int j = 0; j < 8; j++) {
        int q = qblk + tx * 8 + j;
        sqv[j] = g_sq[b * LQ + q];
        qmv[j] = g_qm[b * LQ + q];
    }
    float colpart[8];
#pragma unroll
    for (int j = 0; j < 8; j++) colpart[j] = 0.f;

#pragma unroll
    for (int i = 0; i < 8; i++) {
        int c = cblk + ty * 8 + i;
        float scv = g_sc[b * LC + c];
        int cmv = g_cm[b * LC + c];
        float accv[8];
#pragma unroll
        for (int jp = 0; jp < 4; jp++) {
            float2 p = unpk(acc2[i][jp]);
            accv[2 * jp] = p.x; accv[2 * jp + 1] = p.y;
        }
        float e[8];
        float rowp = 0.f;
#pragma unroll
        for (int j = 0; j < 8; j++) {
            float s = accv[j] + scv + sqv[j];
            float ev = (cmv | qmv[j]) ? 0.f : __expf(s);
            e[j] = ev;
            rowp += ev;
            colpart[j] += ev;
        }
        float* ep = g_E + ((size_t)(b * LC + c)) * LQ + qblk + tx * 8;
        *(float4*)ep       = make_float4(e[0], e[1], e[2], e[3]);
        *(float4*)(ep + 4) = make_float4(e[4], e[5], e[6], e[7]);
#pragma unroll
        for (int o = 8; o; o >>= 1) rowp += __shfl_xor_sync(0xffffffffu, rowp, o, 16);
        if (tx == 0) g_rowsum_part[((size_t)b * 2 + blockIdx.y) * LC + c] = rowp;
    }
#pragma unroll
    for (int j = 0; j < 8; j++) colred[ty][tx * 8 + j] = colpart[j];
    __syncthreads();
    if (tid < BN) {
        float s = 0.f;
#pragma unroll
        for (int t = 0; t < 16; t++) s += colred[t][tid];
        g_colsum_part[((size_t)b * 16 + blockIdx.x) * LQ + qblk + tid] = s;
    }
}

// ---------------- K2: deterministic partial reductions ----------------
__global__ void k2_reduce() {
    int b = blockIdx.x, tid = threadIdx.x;  // 256 threads
    for (int c = tid; c < LC; c += 256) {
        g_rowsum[b * LC + c] = g_rowsum_part[((size_t)b * 2 + 0) * LC + c] +
                               g_rowsum_part[((size_t)b * 2 + 1) * LC + c];
    }
    {
        int q = tid;
        float s = 0.f;
#pragma unroll
        for (int t = 0; t < 16; t++) s += g_colsum_part[((size_t)b * 16 + t) * LQ + q];
        g_colsum[b * LQ + q] = s;
    }
    {
        int d = tid;
        float s = 0.f;
#pragma unroll
        for (int t = 0; t < 8; t++) s += g_cmean_part[((size_t)b * 8 + t) * Dd + d];
        g_cmean[b * Dd + d] = s * (1.0f / LC);
    }
}

// ---------------- K3: T[q][d] = (1/colsum) * sum_c E[c][q]*ctx[c][d] (fallback cmean) -----
__global__ __launch_bounds__(256, 2)
void k3_T(const float* __restrict__ ctx) {
    int b = blockIdx.z;
    int qblk = blockIdx.x * BM;  // 2 tiles
    int dblk = blockIdx.y * BN;  // 2 tiles
    __shared__ float As[KC][BM + PAD];
    __shared__ float Bs[KC][BN + PAD];
    int tid = threadIdx.x, tx = tid & 15, ty = tid >> 4;
    unsigned long long acc2[8][4];
#pragma unroll
    for (int i = 0; i < 8; i++)
#pragma unroll
        for (int j = 0; j < 4; j++) acc2[i][j] = 0ull;

    const float* Ep = g_E + (size_t)b * LC * LQ;
    const float* Cp = ctx + (size_t)b * LC * Dd;

    for (int k0 = 0; k0 < LC; k0 += KC) {
#pragma unroll
        for (int r = 0; r < 4; r++) {
            int u = tid + 256 * r;
            int kk = u >> 5;
            int m4 = (u & 31) * 4;
            *(float4*)&As[kk][m4] = *(const float4*)(Ep + (size_t)(k0 + kk) * LQ + qblk + m4);
            *(float4*)&Bs[kk][m4] = *(const float4*)(Cp + (size_t)(k0 + kk) * Dd + dblk + m4);
        }
        __syncthreads();
        MICRO_FFMA2(As, Bs, acc2)
        __syncthreads();
    }

#pragma unroll
    for (int i = 0; i < 8; i++) {
        int q = qblk + ty * 8 + i;
        float cs = g_colsum[b * LQ + q];
        float* Tp = g_T + ((size_t)b * LQ + q) * Dd + dblk + tx * 8;
        float accv[8];
#pragma unroll
        for (int jp = 0; jp < 4; jp++) {
            float2 p = unpk(acc2[i][jp]);
            accv[2 * jp] = p.x; accv[2 * jp + 1] = p.y;
        }
        if (cs > 0.f) {
            float inv = 1.0f / cs;
            *(float4*)Tp = make_float4(accv[0] * inv, accv[1] * inv,
                                       accv[2] * inv, accv[3] * inv);
            *(float4*)(Tp + 4) = make_float4(accv[4] * inv, accv[5] * inv,
                                             accv[6] * inv, accv[7] * inv);
        } else {
            const float* fb = g_cmean + b * Dd + dblk + tx * 8;
            *(float4*)Tp = make_float4(fb[0], fb[1], fb[2], fb[3]);
            *(float4*)(Tp + 4) = make_float4(fb[4], fb[5], fb[6], fb[7]);
        }
    }
}

// ---------------- K3b: tmean = mean_q T ----------------
__global__ void k3b_tmean() {
    int b = blockIdx.x, d = threadIdx.x;  // 256 threads
    const float* p = g_T + (size_t)b * LQ * Dd + d;
    float s0 = 0, s1 = 0, s2 = 0, s3 = 0;
    for (int q = 0; q < LQ; q += 4) {
        s0 += p[(size_t)(q + 0) * Dd]; s1 += p[(size_t)(q + 1) * Dd];
        s2 += p[(size_t)(q + 2) * Dd]; s3 += p[(size_t)(q + 3) * Dd];
    }
    g_tmean[b * Dd + d] = ((s0 + s1) + (s2 + s3)) * (1.0f / LQ);
}

// ---------------- K4: A = E@query / rowsum ; Bmat = E@T / rowsum (uniform fallbacks) -----
__global__ __launch_bounds__(256, 2)
void k4_out(const float* __restrict__ qry, float* __restrict__ out) {
    int b = blockIdx.z;
    int cblk = blockIdx.x * BM;              // 16 tiles
    int sel = blockIdx.y >> 1;               // 0 = A, 1 = Bmat
    int dblk = (blockIdx.y & 1) * BN;        // 2 tiles
    const float* Bsrc = sel ? (g_T + (size_t)b * LQ * Dd) : (qry + (size_t)b * LQ * Dd);
    const float* fb = (sel ? g_tmean : g_qmean) + b * Dd;
    float* op = out + (size_t)sel * Bb * LC * Dd + (size_t)b * LC * Dd;

    __shared__ float As[KC][BM + PAD];
    __shared__ float Bs[KC][BN + PAD];
    int tid = threadIdx.x, tx = tid & 15, ty = tid >> 4;
    unsigned long long acc2[8][4];
#pragma unroll
    for (int i = 0; i < 8; i++)
#pragma unroll
        for (int j = 0; j < 4; j++) acc2[i][j] = 0ull;

    const float* Ep = g_E + ((size_t)b * LC + cblk) * LQ;

    for (int k0 = 0; k0 < LQ; k0 += KC) {
#pragma unroll
        for (int r = 0; r < 4; r++) {
            int u = tid + 256 * r;
            // A tile: E rows (k = q contiguous) -> transpose into As[k][m]
            int row = u >> 3;
            int kq = (u & 7) * 4;
            float4 v = *(const float4*)(Ep + (size_t)row * LQ + k0 + kq);
            As[kq + 0][row] = v.x; As[kq + 1][row] = v.y;
            As[kq + 2][row] = v.z; As[kq + 3][row] = v.w;
            // B tile: Bsrc[k=q][n=d] directly
            int kk = u >> 5;
            int m4 = (u & 31) * 4;
            *(float4*)&Bs[kk][m4] = *(const float4*)(Bsrc + (size_t)(k0 + kk) * Dd + dblk + m4);
        }
        __syncthreads();
        MICRO_FFMA2(As, Bs, acc2)
        __syncthreads();
    }

#pragma unroll
    for (int i = 0; i < 8; i++) {
        int c = cblk + ty * 8 + i;
        float rs = g_rowsum[b * LC + c];
        float* dst = op + (size_t)c * Dd + dblk + tx * 8;
        float accv[8];
#pragma unroll
        for (int jp = 0; jp < 4; jp++) {
            float2 p = unpk(acc2[i][jp]);
            accv[2 * jp] = p.x; accv[2 * jp + 1] = p.y;
        }
        if (rs > 0.f) {
            float inv = 1.0f / rs;
            *(float4*)dst = make_float4(accv[0] * inv, accv[1] * inv,
                                        accv[2] * inv, accv[3] * inv);
            *(float4*)(dst + 4) = make_float4(accv[4] * inv, accv[5] * inv,
                                              accv[6] * inv, accv[7] * inv);
        } else {
            const float* f = fb + dblk + tx * 8;
            *(float4*)dst = make_float4(f[0], f[1], f[2], f[3]);
            *(float4*)(dst + 4) = make_float4(f[4], f[5], f[6], f[7]);
        }
    }
}

// ---------------- launcher ----------------
extern "C" void kernel_launch(void* const* d_in, const int* in_sizes, int n_in,
                              void* d_out, int out_size) {
    const float* ctx = (const float*)d_in[0];
    const float* qry = (const float*)d_in[1];
    const void* cmask = d_in[2];
    const void* qmask = d_in[3];
    const float* w0 = (const float*)d_in[4];
    float* out = (float*)d_out;

    k_detect<<<1, 32>>>((const unsigned char*)cmask);
    k_cvt_mask<<<(Bb * LC + 255) / 256, 256>>>(cmask, qmask);
    k0_rowdots<<<(Bb * (LC + LQ)) / 8, 256>>>(ctx, qry, w0);
    k0_means<<<dim3(Bb, 9), 256>>>(ctx, qry);
    k1_exp<<<dim3(LC / BM, LQ / BN, Bb), 256>>>(ctx, qry, w0);
    k2_reduce<<<Bb, 256>>>();
    k3_T<<<dim3(LQ / BM, Dd / BN, Bb), 256>>>(ctx);
    k3b_tmean<<<Bb, 256>>>();
    k4_out<<<dim3(LC / BM, 4, Bb), 256>>>(qry, out);
}

// round 14
// speedup vs baseline: 1.2981x; 1.1331x over previous
#include <cuda_runtime.h>
#include <cuda_bf16.h>
#include <math.h>
#include <stdint.h>

// Problem dims
#define Bb 32
#define LC 2048
#define LQ 256
#define Dd 256

// SIMT GEMM tiling (K1/K3)
#define BM 128
#define BN 128
#define KC 32
#define PAD 4   // keeps rows 16B-aligned: (BM+PAD)*4 = 528 bytes

// ---------------- packed f32x2 helpers ----------------
__device__ __forceinline__ unsigned long long dupf2(float x) {
    unsigned long long r;
    asm("mov.b64 %0, {%1, %1};" : "=l"(r) : "f"(x));
    return r;
}
__device__ __forceinline__ void fma2(unsigned long long& d, unsigned long long a,
                                     unsigned long long b) {
    asm("fma.rn.f32x2 %0, %1, %2, %0;" : "+l"(d) : "l"(a), "l"(b));
}
__device__ __forceinline__ float2 unpk(unsigned long long v) {
    float2 f;
    asm("mov.b64 {%0, %1}, %2;" : "=f"(f.x), "=f"(f.y) : "l"(v));
    return f;
}

// ---------------- mma.sync helper (HMMA bf16, baseline PTX, works on sm_103) ----------
#define MMA16816(c, a, bq)                                                              \
    asm volatile(                                                                       \
        "mma.sync.aligned.m16n8k16.row.col.f32.bf16.bf16.f32 "                          \
        "{%0,%1,%2,%3}, {%4,%5,%6,%7}, {%8,%9}, {%0,%1,%2,%3};"                         \
        : "+f"((c)[0]), "+f"((c)[1]), "+f"((c)[2]), "+f"((c)[3])                        \
        : "r"((a)[0]), "r"((a)[1]), "r"((a)[2]), "r"((a)[3]),                           \
          "r"((bq)[0]), "r"((bq)[1]))

// ---------------- scratch (device globals; no allocations allowed) ----------------
__device__ float g_E[(size_t)Bb * LC * LQ];          // exp(sim), 0 at masked  (67 MB)
__device__ float g_T[(size_t)Bb * LQ * Dd];          // T                       (8 MB)
__device__ __nv_bfloat16 g_Eh[(size_t)Bb * LC * LQ]; // E hi split             (32 MB)
__device__ __nv_bfloat16 g_El[(size_t)Bb * LC * LQ]; // E lo split             (32 MB)
__device__ __nv_bfloat16 g_qTh[(size_t)Bb * Dd * LQ];// query^T hi  [d][q]      (4 MB)
__device__ __nv_bfloat16 g_qTl[(size_t)Bb * Dd * LQ];
__device__ __nv_bfloat16 g_TTh[(size_t)Bb * Dd * LQ];// T^T hi      [d][q]      (4 MB)
__device__ __nv_bfloat16 g_TTl[(size_t)Bb * Dd * LQ];
__device__ float g_sc[Bb * LC];
__device__ float g_sq[Bb * LQ];
__device__ float g_rowsum_part[Bb * 2 * LC];
__device__ float g_invrow[Bb * LC];                  // 1/rowsum, 0 if rowsum==0
__device__ float g_colsum_part[Bb * 16 * LQ];
__device__ float g_colsum[Bb * LQ];
__device__ float g_qmean[Bb * Dd];
__device__ float g_cmean_part[Bb * 8 * Dd];
__device__ float g_cmean[Bb * Dd];
__device__ float g_tmean[Bb * Dd];
__device__ unsigned char g_cm[Bb * LC];
__device__ unsigned char g_qm[Bb * LQ];
__device__ int g_is32;

// ---------------- mask dtype detection + canonicalization ----------------
__global__ void k_detect(const unsigned char* __restrict__ cm) {
    if (threadIdx.x == 0 && blockIdx.x == 0) {
        int is32 = 1;
        for (int i = 0; i < 4096; i++) {
            if ((i & 3) && cm[i]) { is32 = 0; break; }
        }
        g_is32 = is32;
    }
}

__global__ void k_cvt_mask(const void* __restrict__ cm, const void* __restrict__ qm) {
    int i = blockIdx.x * 256 + threadIdx.x;
    int is32 = g_is32;
    if (i < Bb * LC) {
        g_cm[i] = is32 ? (unsigned char)(((const int*)cm)[i] != 0)
                       : (unsigned char)(((const unsigned char*)cm)[i] != 0);
    }
    if (i < Bb * LQ) {
        g_qm[i] = is32 ? (unsigned char)(((const int*)qm)[i] != 0)
                       : (unsigned char)(((const unsigned char*)qm)[i] != 0);
    }
}

// ---------------- K0a: sc = context @ wc, sq = query @ wq ----------------
__global__ void k0_rowdots(const float* __restrict__ ctx, const float* __restrict__ qry,
                           const float* __restrict__ w0) {
    int warp = (blockIdx.x * blockDim.x + threadIdx.x) >> 5;
    int lane = threadIdx.x & 31;
    const int nC = Bb * LC;
    const float* src;
    const float* wgt;
    float* dst;
    if (warp < nC) {
        src = ctx + (size_t)warp * Dd; wgt = w0; dst = g_sc + warp;
    } else {
        int r = warp - nC;
        if (r >= Bb * LQ) return;
        src = qry + (size_t)r * Dd; wgt = w0 + Dd; dst = g_sq + r;
    }
    float s = 0.f;
#pragma unroll
    for (int i = 0; i < 2; i++) {
        int idx = (lane + 32 * i) * 4;
        float4 v = *(const float4*)(src + idx);
        float4 w = *(const float4*)(wgt + idx);
        s += v.x * w.x + v.y * w.y + v.z * w.z + v.w * w.w;
    }
#pragma unroll
    for (int o = 16; o; o >>= 1) s += __shfl_xor_sync(0xffffffffu, s, o);
    if (lane == 0) *dst = s;
}

// ---------------- K0b: qmean, cmean partials ----------------
__global__ void k0_means(const float* __restrict__ ctx, const float* __restrict__ qry) {
    int b = blockIdx.x, y = blockIdx.y, d = threadIdx.x;
    if (y == 0) {
        const float* p = qry + (size_t)b * LQ * Dd + d;
        float s0 = 0, s1 = 0, s2 = 0, s3 = 0, s4 = 0, s5 = 0, s6 = 0, s7 = 0;
        for (int q = 0; q < LQ; q += 8) {
            s0 += p[(size_t)(q + 0) * Dd]; s1 += p[(size_t)(q + 1) * Dd];
            s2 += p[(size_t)(q + 2) * Dd]; s3 += p[(size_t)(q + 3) * Dd];
            s4 += p[(size_t)(q + 4) * Dd]; s5 += p[(size_t)(q + 5) * Dd];
            s6 += p[(size_t)(q + 6) * Dd]; s7 += p[(size_t)(q + 7) * Dd];
        }
        g_qmean[b * Dd + d] = (((s0 + s1) + (s2 + s3)) + ((s4 + s5) + (s6 + s7))) * (1.0f / LQ);
    } else {
        int chunk = y - 1;
        const float* p = ctx + ((size_t)b * LC + chunk * 256) * Dd + d;
        float s0 = 0, s1 = 0, s2 = 0, s3 = 0, s4 = 0, s5 = 0, s6 = 0, s7 = 0;
        for (int c = 0; c < 256; c += 8) {
            s0 += p[(size_t)(c + 0) * Dd]; s1 += p[(size_t)(c + 1) * Dd];
            s2 += p[(size_t)(c + 2) * Dd]; s3 += p[(size_t)(c + 3) * Dd];
            s4 += p[(size_t)(c + 4) * Dd]; s5 += p[(size_t)(c + 5) * Dd];
            s6 += p[(size_t)(c + 6) * Dd]; s7 += p[(size_t)(c + 7) * Dd];
        }
        g_cmean_part[((size_t)b * 8 + chunk) * Dd + d] =
            ((s0 + s1) + (s2 + s3)) + ((s4 + s5) + (s6 + s7));
    }
}

// ---------------- bf16 split conversions ----------------
__global__ void k_cvtQT(const float* __restrict__ qry) {
    int q = threadIdx.x, d = blockIdx.y, b = blockIdx.z;
    float v = qry[((size_t)b * LQ + q) * Dd + d];
    __nv_bfloat16 h = __float2bfloat16(v);
    __nv_bfloat16 l = __float2bfloat16(v - __bfloat162float(h));
    size_t o = ((size_t)b * Dd + d) * LQ + q;
    g_qTh[o] = h; g_qTl[o] = l;
}

__global__ void k_cvtTT() {
    int q = threadIdx.x, d = blockIdx.y, b = blockIdx.z;
    float v = g_T[((size_t)b * LQ + q) * Dd + d];
    __nv_bfloat16 h = __float2bfloat16(v);
    __nv_bfloat16 l = __float2bfloat16(v - __bfloat162float(h));
    size_t o = ((size_t)b * Dd + d) * LQ + q;
    g_TTh[o] = h; g_TTl[o] = l;
}

__global__ void k_cvtE() {
    size_t i = ((size_t)blockIdx.x * 256 + threadIdx.x) * 4;
    float4 v = *(const float4*)(g_E + i);
    __nv_bfloat16 h0 = __float2bfloat16(v.x), h1 = __float2bfloat16(v.y);
    __nv_bfloat16 h2 = __float2bfloat16(v.z), h3 = __float2bfloat16(v.w);
    __nv_bfloat16 l0 = __float2bfloat16(v.x - __bfloat162float(h0));
    __nv_bfloat16 l1 = __float2bfloat16(v.y - __bfloat162float(h1));
    __nv_bfloat16 l2 = __float2bfloat16(v.z - __bfloat162float(h2));
    __nv_bfloat16 l3 = __float2bfloat16(v.w - __bfloat162float(h3));
    __nv_bfloat162 ha; ha.x = h0; ha.y = h1;
    __nv_bfloat162 hb; hb.x = h2; hb.y = h3;
    __nv_bfloat162 la; la.x = l0; la.y = l1;
    __nv_bfloat162 lb; lb.x = l2; lb.y = l3;
    *(__nv_bfloat162*)(g_Eh + i)     = ha;
    *(__nv_bfloat162*)(g_Eh + i + 2) = hb;
    *(__nv_bfloat162*)(g_El + i)     = la;
    *(__nv_bfloat162*)(g_El + i + 2) = lb;
}

// ---------------- shared FFMA2 micro-kernel body ----------
#define MICRO_FFMA2(As_, Bs_, acc2_)                                                   \
    _Pragma("unroll 4")                                                                \
    for (int kk = 0; kk < KC; kk++) {                                                  \
        float4 a0 = *(const float4*)&As_[kk][ty * 8];                                  \
        float4 a1 = *(const float4*)&As_[kk][ty * 8 + 4];                              \
        ulonglong2 b01 = *(const ulonglong2*)&Bs_[kk][tx * 8];                         \
        ulonglong2 b23 = *(const ulonglong2*)&Bs_[kk][tx * 8 + 4];                     \
        unsigned long long bb0 = b01.x, bb1 = b01.y, bb2 = b23.x, bb3 = b23.y;         \
        float av[8] = {a0.x, a0.y, a0.z, a0.w, a1.x, a1.y, a1.z, a1.w};                \
        _Pragma("unroll")                                                              \
        for (int i = 0; i < 8; i++) {                                                  \
            unsigned long long aa = dupf2(av[i]);                                      \
            fma2(acc2_[i][0], aa, bb0);                                                \
            fma2(acc2_[i][1], aa, bb1);                                                \
            fma2(acc2_[i][2], aa, bb2);                                                \
            fma2(acc2_[i][3], aa, bb3);                                                \
        }                                                                              \
    }

// ---------------- K1: E = exp(sim) (masked -> 0) + row/col partial sums ----------------
__global__ __launch_bounds__(256, 2)
void k1_exp(const float* __restrict__ ctx, const float* __restrict__ qry,
            const float* __restrict__ w0) {
    int b = blockIdx.z;
    int cblk = blockIdx.x * BM;
    int qblk = blockIdx.y * BN;
    __shared__ float As[KC][BM + PAD];
    __shared__ float Bs[KC][BN + PAD];
    __shared__ float colred[16][BN];
    int tid = threadIdx.x;
    int tx = tid & 15, ty = tid >> 4;
    unsigned long long acc2[8][4];
#pragma unroll
    for (int i = 0; i < 8; i++)
#pragma unroll
        for (int j = 0; j < 4; j++) acc2[i][j] = 0ull;

    const float* wm = w0 + 2 * Dd;
    const float* Ap = ctx + ((size_t)b * LC + cblk) * Dd;
    const float* Bp = qry + ((size_t)b * LQ + qblk) * Dd;

    for (int k0 = 0; k0 < Dd; k0 += KC) {
#pragma unroll
        for (int r = 0; r < 4; r++) {
            int u = tid + 256 * r;
            int row = u >> 3;
            int kq = (u & 7) * 4;
            float4 v = *(const float4*)(Ap + (size_t)row * Dd + k0 + kq);
            float4 w = *(const float4*)(wm + k0 + kq);
            As[kq + 0][row] = v.x * w.x; As[kq + 1][row] = v.y * w.y;
            As[kq + 2][row] = v.z * w.z; As[kq + 3][row] = v.w * w.w;
            float4 q4 = *(const float4*)(Bp + (size_t)row * Dd + k0 + kq);
            Bs[kq + 0][row] = q4.x; Bs[kq + 1][row] = q4.y;
            Bs[kq + 2][row] = q4.z; Bs[kq + 3][row] = q4.w;
        }
        __syncthreads();
        MICRO_FFMA2(As, Bs, acc2)
        __syncthreads();
    }

    float sqv[8];
    int qmv[8];
#pragma unroll
    for (int j = 0; j < 8; j++) {
        int q = qblk + tx * 8 + j;
        sqv[j] = g_sq[b * LQ + q];
        qmv[j] = g_qm[b * LQ + q];
    }
    float colpart[8];
#pragma unroll
    for (int j = 0; j < 8; j++) colpart[j] = 0.f;

#pragma unroll
    for (int i = 0; i < 8; i++) {
        int c = cblk + ty * 8 + i;
        float scv = g_sc[b * LC + c];
        int cmv = g_cm[b * LC + c];
        float accv[8];
#pragma unroll
        for (int jp = 0; jp < 4; jp++) {
            float2 p = unpk(acc2[i][jp]);
            accv[2 * jp] = p.x; accv[2 * jp + 1] = p.y;
        }
        float e[8];
        float rowp = 0.f;
#pragma unroll
        for (int j = 0; j < 8; j++) {
            float s = accv[j] + scv + sqv[j];
            float ev = (cmv | qmv[j]) ? 0.f : __expf(s);
            e[j] = ev;
            rowp += ev;
            colpart[j] += ev;
        }
        float* ep = g_E + ((size_t)(b * LC + c)) * LQ + qblk + tx * 8;
        *(float4*)ep       = make_float4(e[0], e[1], e[2], e[3]);
        *(float4*)(ep + 4) = make_float4(e[4], e[5], e[6], e[7]);
#pragma unroll
        for (int o = 8; o; o >>= 1) rowp += __shfl_xor_sync(0xffffffffu, rowp, o, 16);
        if (tx == 0) g_rowsum_part[((size_t)b * 2 + blockIdx.y) * LC + c] = rowp;
    }
#pragma unroll
    for (int j = 0; j < 8; j++) colred[ty][tx * 8 + j] = colpart[j];
    __syncthreads();
    if (tid < BN) {
        float s = 0.f;
#pragma unroll
        for (int t = 0; t < 16; t++) s += colred[t][tid];
        g_colsum_part[((size_t)b * 16 + blockIdx.x) * LQ + qblk + tid] = s;
    }
}

// ---------------- K2: deterministic partial reductions ----------------
__global__ void k2_reduce() {
    int b = blockIdx.x, tid = threadIdx.x;
    for (int c = tid; c < LC; c += 256) {
        float rs = g_rowsum_part[((size_t)b * 2 + 0) * LC + c] +
                   g_rowsum_part[((size_t)b * 2 + 1) * LC + c];
        g_invrow[b * LC + c] = rs > 0.f ? 1.0f / rs : 0.f;
    }
    {
        int q = tid;
        float s = 0.f;
#pragma unroll
        for (int t = 0; t < 16; t++) s += g_colsum_part[((size_t)b * 16 + t) * LQ + q];
        g_colsum[b * LQ + q] = s;
    }
    {
        int d = tid;
        float s = 0.f;
#pragma unroll
        for (int t = 0; t < 8; t++) s += g_cmean_part[((size_t)b * 8 + t) * Dd + d];
        g_cmean[b * Dd + d] = s * (1.0f / LC);
    }
}

// ---------------- K3: T[q][d] (SIMT FFMA2) ----------------
__global__ __launch_bounds__(256, 2)
void k3_T(const float* __restrict__ ctx) {
    int b = blockIdx.z;
    int qblk = blockIdx.x * BM;
    int dblk = blockIdx.y * BN;
    __shared__ float As[KC][BM + PAD];
    __shared__ float Bs[KC][BN + PAD];
    int tid = threadIdx.x, tx = tid & 15, ty = tid >> 4;
    unsigned long long acc2[8][4];
#pragma unroll
    for (int i = 0; i < 8; i++)
#pragma unroll
        for (int j = 0; j < 4; j++) acc2[i][j] = 0ull;

    const float* Ep = g_E + (size_t)b * LC * LQ;
    const float* Cp = ctx + (size_t)b * LC * Dd;

    for (int k0 = 0; k0 < LC; k0 += KC) {
#pragma unroll
        for (int r = 0; r < 4; r++) {
            int u = tid + 256 * r;
            int kk = u >> 5;
            int m4 = (u & 31) * 4;
            *(float4*)&As[kk][m4] = *(const float4*)(Ep + (size_t)(k0 + kk) * LQ + qblk + m4);
            *(float4*)&Bs[kk][m4] = *(const float4*)(Cp + (size_t)(k0 + kk) * Dd + dblk + m4);
        }
        __syncthreads();
        MICRO_FFMA2(As, Bs, acc2)
        __syncthreads();
    }

#pragma unroll
    for (int i = 0; i < 8; i++) {
        int q = qblk + ty * 8 + i;
        float cs = g_colsum[b * LQ + q];
        float* Tp = g_T + ((size_t)b * LQ + q) * Dd + dblk + tx * 8;
        float accv[8];
#pragma unroll
        for (int jp = 0; jp < 4; jp++) {
            float2 p = unpk(acc2[i][jp]);
            accv[2 * jp] = p.x; accv[2 * jp + 1] = p.y;
        }
        if (cs > 0.f) {
            float inv = 1.0f / cs;
            *(float4*)Tp = make_float4(accv[0] * inv, accv[1] * inv,
                                       accv[2] * inv, accv[3] * inv);
            *(float4*)(Tp + 4) = make_float4(accv[4] * inv, accv[5] * inv,
                                             accv[6] * inv, accv[7] * inv);
        } else {
            const float* fb = g_cmean + b * Dd + dblk + tx * 8;
            *(float4*)Tp = make_float4(fb[0], fb[1], fb[2], fb[3]);
            *(float4*)(Tp + 4) = make_float4(fb[4], fb[5], fb[6], fb[7]);
        }
    }
}

// ---------------- K3b: tmean = mean_q T ----------------
__global__ void k3b_tmean() {
    int b = blockIdx.x, d = threadIdx.x;
    const float* p = g_T + (size_t)b * LQ * Dd + d;
    float s0 = 0, s1 = 0, s2 = 0, s3 = 0;
    for (int q = 0; q < LQ; q += 4) {
        s0 += p[(size_t)(q + 0) * Dd]; s1 += p[(size_t)(q + 1) * Dd];
        s2 += p[(size_t)(q + 2) * Dd]; s3 += p[(size_t)(q + 3) * Dd];
    }
    g_tmean[b * Dd + d] = ((s0 + s1) + (s2 + s3)) * (1.0f / LQ);
}

// ---------------- K4 (HMMA): Out[c][d] = (1/rowsum[c]) * sum_q E[c][q] * Bsrc[q][d] ----
// A = E[c][q] row-major (hi/lo), B = qT/TT [d][q] (col-major k x n for mma). 2-term split.
// CTA: 128c x 128d, k-chunks of 32. 8 warps as 2(m) x 4(n); warp tile 64m x 32n.
#define K4ST 40   // smem row stride in bf16 (80 B = 5*16B, bank-conflict-free)
__global__ __launch_bounds__(256)
void k4_mma(float* __restrict__ out) {
    __shared__ __nv_bfloat16 sEh[128 * K4ST];
    __shared__ __nv_bfloat16 sEl[128 * K4ST];
    __shared__ __nv_bfloat16 sQh[128 * K4ST];
    __shared__ __nv_bfloat16 sQl[128 * K4ST];

    int tid = threadIdx.x, wid = tid >> 5, lane = tid & 31;
    int b = blockIdx.z;
    int cblk = blockIdx.x * 128;
    int sel = blockIdx.y >> 1;
    int dblk = (blockIdx.y & 1) * 128;

    const __nv_bfloat16* Eh = g_Eh + ((size_t)b * LC + cblk) * LQ;
    const __nv_bfloat16* El = g_El + ((size_t)b * LC + cblk) * LQ;
    const __nv_bfloat16* Qh = (sel ? g_TTh : g_qTh) + ((size_t)b * Dd + dblk) * LQ;
    const __nv_bfloat16* Ql = (sel ? g_TTl : g_qTl) + ((size_t)b * Dd + dblk) * LQ;
    const float* fb = (sel ? g_tmean : g_qmean) + b * Dd;
    float* op = out + (size_t)sel * Bb * LC * Dd + (size_t)b * LC * Dd;

    int wm = wid & 1;        // 0..1 -> m offset 64*wm
    int wn = wid >> 1;       // 0..3 -> n offset 32*wn
    int g = lane >> 2;       // 0..7
    int qi = lane & 3;       // 0..3

    float acc[4][4][4];
#pragma unroll
    for (int mi = 0; mi < 4; mi++)
#pragma unroll
        for (int ni = 0; ni < 4; ni++)
#pragma unroll
            for (int r = 0; r < 4; r++) acc[mi][ni][r] = 0.f;

    for (int ko = 0; ko < LQ; ko += 32) {
        // load 4 tiles of [128 rows][32 bf16]; 512 x 16B chunks per tile, 2 per thread
#pragma unroll
        for (int j = 0; j < 2; j++) {
            int cid = tid * 2 + j;          // 0..511
            int row = cid >> 2;
            int c8 = (cid & 3) * 8;
            size_t go = (size_t)row * LQ + ko + c8;
            int so = row * K4ST + c8;
            *(uint4*)&sEh[so] = *(const uint4*)(Eh + go);
            *(uint4*)&sEl[so] = *(const uint4*)(El + go);
            *(uint4*)&sQh[so] = *(const uint4*)(Qh + go);
            *(uint4*)&sQl[so] = *(const uint4*)(Ql + go);
        }
        __syncthreads();

#pragma unroll
        for (int s = 0; s < 2; s++) {
            int kl = s * 16;
            // A fragments (E): m16 blocks at wm*64 + mi*16
            uint32_t ah[4][4], al[4][4];
#pragma unroll
            for (int mi = 0; mi < 4; mi++) {
                int off = (wm * 64 + mi * 16 + g) * K4ST + kl + qi * 2;
                ah[mi][0] = *(const uint32_t*)&sEh[off];
                ah[mi][1] = *(const uint32_t*)&sEh[off + 8 * K4ST];
                ah[mi][2] = *(const uint32_t*)&sEh[off + 8];
                ah[mi][3] = *(const uint32_t*)&sEh[off + 8 * K4ST + 8];
                al[mi][0] = *(const uint32_t*)&sEl[off];
                al[mi][1] = *(const uint32_t*)&sEl[off + 8 * K4ST];
                al[mi][2] = *(const uint32_t*)&sEl[off + 8];
                al[mi][3] = *(const uint32_t*)&sEl[off + 8 * K4ST + 8];
            }
            // B fragments (Q): n8 blocks at wn*32 + ni*8
            uint32_t bh[4][2], bl[4][2];
#pragma unroll
            for (int ni = 0; ni < 4; ni++) {
                int off = (wn * 32 + ni * 8 + g) * K4ST + kl + qi * 2;
                bh[ni][0] = *(const uint32_t*)&sQh[off];
                bh[ni][1] = *(const uint32_t*)&sQh[off + 8];
                bl[ni][0] = *(const uint32_t*)&sQl[off];
                bl[ni][1] = *(const uint32_t*)&sQl[off + 8];
            }
#pragma unroll
            for (int mi = 0; mi < 4; mi++)
#pragma unroll
                for (int ni = 0; ni < 4; ni++) {
                    MMA16816(acc[mi][ni], ah[mi], bh[ni]);
                    MMA16816(acc[mi][ni], al[mi], bh[ni]);
                    MMA16816(acc[mi][ni], ah[mi], bl[ni]);
                }
        }
        __syncthreads();
    }

    // epilogue: c rows scale by invrow (fallback fb[d]); c0,c1 -> row g; c2,c3 -> row g+8
#pragma unroll
    for (int ni = 0; ni < 4; ni++) {
        int dcol = dblk + wn * 32 + ni * 8 + qi * 2;
        float fb0 = fb[dcol], fb1 = fb[dcol + 1];
#pragma unroll
        for (int mi = 0; mi < 4; mi++) {
            int c0 = cblk + wm * 64 + mi * 16 + g;
            int c1 = c0 + 8;
            float inv0 = g_invrow[b * LC + c0];
            float inv1 = g_invrow[b * LC + c1];
            float2 v0, v1;
            if (inv0 > 0.f) { v0.x = acc[mi][ni][0] * inv0; v0.y = acc[mi][ni][1] * inv0; }
            else            { v0.x = fb0; v0.y = fb1; }
            if (inv1 > 0.f) { v1.x = acc[mi][ni][2] * inv1; v1.y = acc[mi][ni][3] * inv1; }
            else            { v1.x = fb0; v1.y = fb1; }
            *(float2*)(op + (size_t)c0 * Dd + dcol) = v0;
            *(float2*)(op + (size_t)c1 * Dd + dcol) = v1;
        }
    }
}

// ---------------- launcher ----------------
extern "C" void kernel_launch(void* const* d_in, const int* in_sizes, int n_in,
                              void* d_out, int out_size) {
    const float* ctx = (const float*)d_in[0];
    const float* qry = (const float*)d_in[1];
    const void* cmask = d_in[2];
    const void* qmask = d_in[3];
    const float* w0 = (const float*)d_in[4];
    float* out = (float*)d_out;

    k_detect<<<1, 32>>>((const unsigned char*)cmask);
    k_cvt_mask<<<(Bb * LC + 255) / 256, 256>>>(cmask, qmask);
    k0_rowdots<<<(Bb * (LC + LQ)) / 8, 256>>>(ctx, qry, w0);
    k0_means<<<dim3(Bb, 9), 256>>>(ctx, qry);
    k_cvtQT<<<dim3(1, Dd, Bb), LQ>>>(qry);
    k1_exp<<<dim3(LC / BM, LQ / BN, Bb), 256>>>(ctx, qry, w0);
    k2_reduce<<<Bb, 256>>>();
    k_cvtE<<<(int)(((size_t)Bb * LC * LQ / 4) / 256), 256>>>();
    k3_T<<<dim3(LQ / BM, Dd / BN, Bb), 256>>>(ctx);
    k3b_tmean<<<Bb, 256>>>();
    k_cvtTT<<<dim3(1, Dd, Bb), LQ>>>();
    k4_mma<<<dim3(LC / 128, 4, Bb), 256>>>(out);
}

// round 15
// speedup vs baseline: 1.5014x; 1.1566x over previous
#include <cuda_runtime.h>
#include <cuda_bf16.h>
#include <math.h>
#include <stdint.h>

// Problem dims
#define Bb 32
#define LC 2048
#define LQ 256
#define Dd 256

// ---------------- mma.sync helper (HMMA bf16, baseline PTX, works on sm_103) ----------
#define MMA16816(c, a, bq)                                                              \
    asm volatile(                                                                       \
        "mma.sync.aligned.m16n8k16.row.col.f32.bf16.bf16.f32 "                          \
        "{%0,%1,%2,%3}, {%4,%5,%6,%7}, {%8,%9}, {%0,%1,%2,%3};"                         \
        : "+f"((c)[0]), "+f"((c)[1]), "+f"((c)[2]), "+f"((c)[3])                        \
        : "r"((a)[0]), "r"((a)[1]), "r"((a)[2]), "r"((a)[3]),                           \
          "r"((bq)[0]), "r"((bq)[1]))

// ---------------- scratch (device globals; no allocations allowed) ----------------
__device__ float g_T[(size_t)Bb * LQ * Dd];          // T fp32                 (8 MB)
__device__ __nv_bfloat16 g_Eh[(size_t)Bb * LC * LQ]; // E hi split [c][q]      (32 MB)
__device__ __nv_bfloat16 g_El[(size_t)Bb * LC * LQ]; // E lo split             (32 MB)
__device__ __nv_bfloat16 g_ch[(size_t)Bb * LC * Dd]; // ctx hi split [c][d]    (32 MB)
__device__ __nv_bfloat16 g_cl[(size_t)Bb * LC * Dd];
__device__ __nv_bfloat16 g_qwh[(size_t)Bb * LQ * Dd];// (qry*wm) hi [q][d]      (4 MB)
__device__ __nv_bfloat16 g_qwl[(size_t)Bb * LQ * Dd];
__device__ __nv_bfloat16 g_qTh[(size_t)Bb * Dd * LQ];// query^T hi [d][q]       (4 MB)
__device__ __nv_bfloat16 g_qTl[(size_t)Bb * Dd * LQ];
__device__ __nv_bfloat16 g_TTh[(size_t)Bb * Dd * LQ];// T^T hi     [d][q]       (4 MB)
__device__ __nv_bfloat16 g_TTl[(size_t)Bb * Dd * LQ];
__device__ float g_sc[Bb * LC];
__device__ float g_sq[Bb * LQ];
__device__ float g_rowsum_part[Bb * 2 * LC];
__device__ float g_invrow[Bb * LC];                  // 1/rowsum, 0 if rowsum==0
__device__ float g_colsum_part[Bb * 16 * LQ];
__device__ float g_colsum[Bb * LQ];
__device__ float g_qmean[Bb * Dd];
__device__ float g_cmean_part[Bb * 8 * Dd];
__device__ float g_cmean[Bb * Dd];
__device__ float g_tmean[Bb * Dd];
__device__ unsigned char g_cm[Bb * LC];
__device__ unsigned char g_qm[Bb * LQ];
__device__ int g_is32;

// ---------------- mask dtype detection + canonicalization ----------------
__global__ void k_detect(const unsigned char* __restrict__ cm) {
    if (threadIdx.x == 0 && blockIdx.x == 0) {
        int is32 = 1;
        for (int i = 0; i < 4096; i++) {
            if ((i & 3) && cm[i]) { is32 = 0; break; }
        }
        g_is32 = is32;
    }
}

__global__ void k_cvt_mask(const void* __restrict__ cm, const void* __restrict__ qm) {
    int i = blockIdx.x * 256 + threadIdx.x;
    int is32 = g_is32;
    if (i < Bb * LC) {
        g_cm[i] = is32 ? (unsigned char)(((const int*)cm)[i] != 0)
                       : (unsigned char)(((const unsigned char*)cm)[i] != 0);
    }
    if (i < Bb * LQ) {
        g_qm[i] = is32 ? (unsigned char)(((const int*)qm)[i] != 0)
                       : (unsigned char)(((const unsigned char*)qm)[i] != 0);
    }
}

// ---------------- K0a: sc = context @ wc, sq = query @ wq ----------------
__global__ void k0_rowdots(const float* __restrict__ ctx, const float* __restrict__ qry,
                           const float* __restrict__ w0) {
    int warp = (blockIdx.x * blockDim.x + threadIdx.x) >> 5;
    int lane = threadIdx.x & 31;
    const int nC = Bb * LC;
    const float* src;
    const float* wgt;
    float* dst;
    if (warp < nC) {
        src = ctx + (size_t)warp * Dd; wgt = w0; dst = g_sc + warp;
    } else {
        int r = warp - nC;
        if (r >= Bb * LQ) return;
        src = qry + (size_t)r * Dd; wgt = w0 + Dd; dst = g_sq + r;
    }
    float s = 0.f;
#pragma unroll
    for (int i = 0; i < 2; i++) {
        int idx = (lane + 32 * i) * 4;
        float4 v = *(const float4*)(src + idx);
        float4 w = *(const float4*)(wgt + idx);
        s += v.x * w.x + v.y * w.y + v.z * w.z + v.w * w.w;
    }
#pragma unroll
    for (int o = 16; o; o >>= 1) s += __shfl_xor_sync(0xffffffffu, s, o);
    if (lane == 0) *dst = s;
}

// ---------------- K0b: qmean, cmean partials ----------------
__global__ void k0_means(const float* __restrict__ ctx, const float* __restrict__ qry) {
    int b = blockIdx.x, y = blockIdx.y, d = threadIdx.x;
    if (y == 0) {
        const float* p = qry + (size_t)b * LQ * Dd + d;
        float s0 = 0, s1 = 0, s2 = 0, s3 = 0, s4 = 0, s5 = 0, s6 = 0, s7 = 0;
        for (int q = 0; q < LQ; q += 8) {
            s0 += p[(size_t)(q + 0) * Dd]; s1 += p[(size_t)(q + 1) * Dd];
            s2 += p[(size_t)(q + 2) * Dd]; s3 += p[(size_t)(q + 3) * Dd];
            s4 += p[(size_t)(q + 4) * Dd]; s5 += p[(size_t)(q + 5) * Dd];
            s6 += p[(size_t)(q + 6) * Dd]; s7 += p[(size_t)(q + 7) * Dd];
        }
        g_qmean[b * Dd + d] = (((s0 + s1) + (s2 + s3)) + ((s4 + s5) + (s6 + s7))) * (1.0f / LQ);
    } else {
        int chunk = y - 1;
        const float* p = ctx + ((size_t)b * LC + chunk * 256) * Dd + d;
        float s0 = 0, s1 = 0, s2 = 0, s3 = 0, s4 = 0, s5 = 0, s6 = 0, s7 = 0;
        for (int c = 0; c < 256; c += 8) {
            s0 += p[(size_t)(c + 0) * Dd]; s1 += p[(size_t)(c + 1) * Dd];
            s2 += p[(size_t)(c + 2) * Dd]; s3 += p[(size_t)(c + 3) * Dd];
            s4 += p[(size_t)(c + 4) * Dd]; s5 += p[(size_t)(c + 5) * Dd];
            s6 += p[(size_t)(c + 6) * Dd]; s7 += p[(size_t)(c + 7) * Dd];
        }
        g_cmean_part[((size_t)b * 8 + chunk) * Dd + d] =
            ((s0 + s1) + (s2 + s3)) + ((s4 + s5) + (s6 + s7));
    }
}

// ---------------- bf16 split conversions ----------------
__device__ __forceinline__ void split2(float x, float y, __nv_bfloat162& h, __nv_bfloat162& l) {
    __nv_bfloat16 hx = __float2bfloat16(x), hy = __float2bfloat16(y);
    h.x = hx; h.y = hy;
    l.x = __float2bfloat16(x - __bfloat162float(hx));
    l.y = __float2bfloat16(y - __bfloat162float(hy));
}

__global__ void k_cvtC(const float* __restrict__ ctx) {
    size_t i = ((size_t)blockIdx.x * 256 + threadIdx.x) * 4;
    float4 v = *(const float4*)(ctx + i);
    __nv_bfloat162 h0, l0, h1, l1;
    split2(v.x, v.y, h0, l0);
    split2(v.z, v.w, h1, l1);
    *(__nv_bfloat162*)(g_ch + i) = h0;     *(__nv_bfloat162*)(g_ch + i + 2) = h1;
    *(__nv_bfloat162*)(g_cl + i) = l0;     *(__nv_bfloat162*)(g_cl + i + 2) = l1;
}

__global__ void k_cvtQW(const float* __restrict__ qry, const float* __restrict__ w0) {
    size_t i = ((size_t)blockIdx.x * 256 + threadIdx.x) * 4;
    int d = (int)(i & (Dd - 1));
    float4 v = *(const float4*)(qry + i);
    float4 w = *(const float4*)(w0 + 2 * Dd + d);
    v.x *= w.x; v.y *= w.y; v.z *= w.z; v.w *= w.w;
    __nv_bfloat162 h0, l0, h1, l1;
    split2(v.x, v.y, h0, l0);
    split2(v.z, v.w, h1, l1);
    *(__nv_bfloat162*)(g_qwh + i) = h0;    *(__nv_bfloat162*)(g_qwh + i + 2) = h1;
    *(__nv_bfloat162*)(g_qwl + i) = l0;    *(__nv_bfloat162*)(g_qwl + i + 2) = l1;
}

__global__ void k_cvtQT(const float* __restrict__ qry) {
    int q = threadIdx.x, d = blockIdx.y, b = blockIdx.z;
    float v = qry[((size_t)b * LQ + q) * Dd + d];
    __nv_bfloat16 h = __float2bfloat16(v);
    __nv_bfloat16 l = __float2bfloat16(v - __bfloat162float(h));
    size_t o = ((size_t)b * Dd + d) * LQ + q;
    g_qTh[o] = h; g_qTl[o] = l;
}

__global__ void k_cvtTT() {
    int q = threadIdx.x, d = blockIdx.y, b = blockIdx.z;
    float v = g_T[((size_t)b * LQ + q) * Dd + d];
    __nv_bfloat16 h = __float2bfloat16(v);
    __nv_bfloat16 l = __float2bfloat16(v - __bfloat162float(h));
    size_t o = ((size_t)b * Dd + d) * LQ + q;
    g_TTh[o] = h; g_TTl[o] = l;
}

// ---------------- K1 (HMMA): sim = ctx @ (qry*wm)^T + sc + sq; E = exp(masked sim) -----
// A = ctx split [c][d] (k=d contig), B = qw split [q][d] (k=d contig). m=128c, n=128q.
#define ST1 40   // smem row stride in bf16 (80 B; conflict-free fragment loads)
__global__ __launch_bounds__(256)
void k1_mma() {
    __shared__ __nv_bfloat16 sAh[128 * ST1];
    __shared__ __nv_bfloat16 sAl[128 * ST1];
    __shared__ __nv_bfloat16 sBh[128 * ST1];
    __shared__ __nv_bfloat16 sBl[128 * ST1];
    __shared__ float s_rp[4][128];
    __shared__ float s_cp[2][128];

    int tid = threadIdx.x, wid = tid >> 5, lane = tid & 31;
    int b = blockIdx.z;
    int cblk = blockIdx.x * 128;
    int qblk = blockIdx.y * 128;

    const __nv_bfloat16* Ah = g_ch + ((size_t)b * LC + cblk) * Dd;
    const __nv_bfloat16* Al = g_cl + ((size_t)b * LC + cblk) * Dd;
    const __nv_bfloat16* Bh = g_qwh + ((size_t)b * LQ + qblk) * Dd;
    const __nv_bfloat16* Bl = g_qwl + ((size_t)b * LQ + qblk) * Dd;

    int wm = wid & 1;        // m offset 64*wm (c)
    int wn = wid >> 1;       // n offset 32*wn (q)
    int g = lane >> 2;
    int qi = lane & 3;

    float acc[4][4][4];
#pragma unroll
    for (int mi = 0; mi < 4; mi++)
#pragma unroll
        for (int ni = 0; ni < 4; ni++)
#pragma unroll
            for (int r = 0; r < 4; r++) acc[mi][ni][r] = 0.f;

    for (int ko = 0; ko < Dd; ko += 32) {
#pragma unroll
        for (int j = 0; j < 2; j++) {
            int cid = tid * 2 + j;
            int row = cid >> 2;
            int c8 = (cid & 3) * 8;
            size_t go = (size_t)row * Dd + ko + c8;
            int so = row * ST1 + c8;
            *(uint4*)&sAh[so] = *(const uint4*)(Ah + go);
            *(uint4*)&sAl[so] = *(const uint4*)(Al + go);
            *(uint4*)&sBh[so] = *(const uint4*)(Bh + go);
            *(uint4*)&sBl[so] = *(const uint4*)(Bl + go);
        }
        __syncthreads();
#pragma unroll
        for (int s = 0; s < 2; s++) {
            int kl = s * 16;
            uint32_t ah[4][4], al[4][4];
#pragma unroll
            for (int mi = 0; mi < 4; mi++) {
                int off = (wm * 64 + mi * 16 + g) * ST1 + kl + qi * 2;
                ah[mi][0] = *(const uint32_t*)&sAh[off];
                ah[mi][1] = *(const uint32_t*)&sAh[off + 8 * ST1];
                ah[mi][2] = *(const uint32_t*)&sAh[off + 8];
                ah[mi][3] = *(const uint32_t*)&sAh[off + 8 * ST1 + 8];
                al[mi][0] = *(const uint32_t*)&sAl[off];
                al[mi][1] = *(const uint32_t*)&sAl[off + 8 * ST1];
                al[mi][2] = *(const uint32_t*)&sAl[off + 8];
                al[mi][3] = *(const uint32_t*)&sAl[off + 8 * ST1 + 8];
            }
            uint32_t bh[4][2], bl[4][2];
#pragma unroll
            for (int ni = 0; ni < 4; ni++) {
                int off = (wn * 32 + ni * 8 + g) * ST1 + kl + qi * 2;
                bh[ni][0] = *(const uint32_t*)&sBh[off];
                bh[ni][1] = *(const uint32_t*)&sBh[off + 8];
                bl[ni][0] = *(const uint32_t*)&sBl[off];
                bl[ni][1] = *(const uint32_t*)&sBl[off + 8];
            }
#pragma unroll
            for (int mi = 0; mi < 4; mi++)
#pragma unroll
                for (int ni = 0; ni < 4; ni++) {
                    MMA16816(acc[mi][ni], ah[mi], bh[ni]);
                    MMA16816(acc[mi][ni], al[mi], bh[ni]);
                    MMA16816(acc[mi][ni], ah[mi], bl[ni]);
                }
        }
        __syncthreads();
    }

    // ---- epilogue: sim -> E, splits, partial sums ----
    float scv[4][2]; int cmv[4][2]; int crow[4][2];
#pragma unroll
    for (int mi = 0; mi < 4; mi++)
#pragma unroll
        for (int h = 0; h < 2; h++) {
            int c = cblk + wm * 64 + mi * 16 + g + h * 8;
            crow[mi][h] = c;
            scv[mi][h] = g_sc[b * LC + c];
            cmv[mi][h] = g_cm[b * LC + c];
        }
    float sqv[4][2]; int qmv[4][2]; int qcol[4];
#pragma unroll
    for (int ni = 0; ni < 4; ni++) {
        int q = qblk + wn * 32 + ni * 8 + qi * 2;
        qcol[ni] = q;
        sqv[ni][0] = g_sq[b * LQ + q];     qmv[ni][0] = g_qm[b * LQ + q];
        sqv[ni][1] = g_sq[b * LQ + q + 1]; qmv[ni][1] = g_qm[b * LQ + q + 1];
    }

    float rowp[4][2]; float colp[4][2];
#pragma unroll
    for (int i = 0; i < 4; i++) { rowp[i][0] = rowp[i][1] = colp[i][0] = colp[i][1] = 0.f; }

#pragma unroll
    for (int mi = 0; mi < 4; mi++)
#pragma unroll
        for (int ni = 0; ni < 4; ni++) {
            float e[4];
#pragma unroll
            for (int r = 0; r < 4; r++) {
                int h = r >> 1, jj = r & 1;
                float s = acc[mi][ni][r] + scv[mi][h] + sqv[ni][jj];
                e[r] = (cmv[mi][h] | qmv[ni][jj]) ? 0.f : __expf(s);
            }
            rowp[mi][0] += e[0] + e[1];
            rowp[mi][1] += e[2] + e[3];
            colp[ni][0] += e[0] + e[2];
            colp[ni][1] += e[1] + e[3];
#pragma unroll
            for (int h = 0; h < 2; h++) {
                __nv_bfloat162 hh, ll;
                split2(e[h * 2], e[h * 2 + 1], hh, ll);
                size_t idx = (size_t)(b * LC + crow[mi][h]) * LQ + qcol[ni];
                *(__nv_bfloat162*)(g_Eh + idx) = hh;
                *(__nv_bfloat162*)(g_El + idx) = ll;
            }
        }

    // row partials: reduce over qi quad, write per-wn slice
#pragma unroll
    for (int mi = 0; mi < 4; mi++)
#pragma unroll
        for (int h = 0; h < 2; h++) {
            float v = rowp[mi][h];
            v += __shfl_xor_sync(0xffffffffu, v, 1);
            v += __shfl_xor_sync(0xffffffffu, v, 2);
            if (qi == 0) s_rp[wn][wm * 64 + mi * 16 + g + h * 8] = v;
        }
    // col partials: reduce over g, write per-wm slice
#pragma unroll
    for (int ni = 0; ni < 4; ni++)
#pragma unroll
        for (int jj = 0; jj < 2; jj++) {
            float v = colp[ni][jj];
            v += __shfl_xor_sync(0xffffffffu, v, 4);
            v += __shfl_xor_sync(0xffffffffu, v, 8);
            v += __shfl_xor_sync(0xffffffffu, v, 16);
            if (lane < 4) s_cp[wm][wn * 32 + ni * 8 + qi * 2 + jj] = v;
        }
    __syncthreads();
    if (tid < 128) {
        float r = s_rp[0][tid] + s_rp[1][tid] + s_rp[2][tid] + s_rp[3][tid];
        g_rowsum_part[((size_t)b * 2 + blockIdx.y) * LC + cblk + tid] = r;
        float cs = s_cp[0][tid] + s_cp[1][tid];
        g_colsum_part[((size_t)b * 16 + blockIdx.x) * LQ + qblk + tid] = cs;
    }
}

// ---------------- K2: deterministic partial reductions ----------------
__global__ void k2_reduce() {
    int b = blockIdx.x, tid = threadIdx.x;
    for (int c = tid; c < LC; c += 256) {
        float rs = g_rowsum_part[((size_t)b * 2 + 0) * LC + c] +
                   g_rowsum_part[((size_t)b * 2 + 1) * LC + c];
        g_invrow[b * LC + c] = rs > 0.f ? 1.0f / rs : 0.f;
    }
    {
        int q = tid;
        float s = 0.f;
#pragma unroll
        for (int t = 0; t < 16; t++) s += g_colsum_part[((size_t)b * 16 + t) * LQ + q];
        g_colsum[b * LQ + q] = s;
    }
    {
        int d = tid;
        float s = 0.f;
#pragma unroll
        for (int t = 0; t < 8; t++) s += g_cmean_part[((size_t)b * 8 + t) * Dd + d];
        g_cmean[b * Dd + d] = s * (1.0f / LC);
    }
}

// ---------------- K3 (HMMA): T[q][d] = (1/colsum[q]) * sum_c E[c][q]*ctx[c][d] ----------
// A = E [c][q] -> transposed to smem [q][c-chunk]; B = ctx [c][d] -> smem [d][c-chunk].
// XOR swizzle keeps both transpose-stores and fragment loads near conflict-free.
__device__ __forceinline__ int swz3(int r, int p) {   // r = row, p = c-pair index (0..15)
    return r * 32 + (((p ^ (r >> 3)) & 15) << 1);
}
__global__ __launch_bounds__(256)
void k3_mma() {
    __shared__ __nv_bfloat16 sAh[128 * 32];
    __shared__ __nv_bfloat16 sAl[128 * 32];
    __shared__ __nv_bfloat16 sBh[128 * 32];
    __shared__ __nv_bfloat16 sBl[128 * 32];

    int tid = threadIdx.x, wid = tid >> 5, lane = tid & 31;
    int b = blockIdx.z;
    int qblk = blockIdx.x * 128;   // m tile (q)
    int dblk = blockIdx.y * 128;   // n tile (d)

    const __nv_bfloat16* Eh = g_Eh + (size_t)b * LC * LQ;
    const __nv_bfloat16* El = g_El + (size_t)b * LC * LQ;
    const __nv_bfloat16* Ch = g_ch + (size_t)b * LC * Dd;
    const __nv_bfloat16* Cl = g_cl + (size_t)b * LC * Dd;

    int wm = wid & 1;        // m offset 64*wm (q)
    int wn = wid >> 1;       // n offset 32*wn (d)
    int g = lane >> 2;
    int qi = lane & 3;

    float acc[4][4][4];
#pragma unroll
    for (int mi = 0; mi < 4; mi++)
#pragma unroll
        for (int ni = 0; ni < 4; ni++)
#pragma unroll
            for (int r = 0; r < 4; r++) acc[mi][ni][r] = 0.f;

    for (int ko = 0; ko < LC; ko += 32) {
#pragma unroll
        for (int j = 0; j < 2; j++) {
            int cid = tid * 2 + j;
            int crow = cid >> 4;          // 0..31 (c within chunk)
            int r8 = (cid & 15) * 8;      // row octet (q or d)
            int cp = crow >> 1, cb = crow & 1;
            uint4 va = *(const uint4*)(Eh + (size_t)(ko + crow) * LQ + qblk + r8);
            uint4 vb = *(const uint4*)(El + (size_t)(ko + crow) * LQ + qblk + r8);
            uint4 vc = *(const uint4*)(Ch + (size_t)(ko + crow) * Dd + dblk + r8);
            uint4 vd = *(const uint4*)(Cl + (size_t)(ko + crow) * Dd + dblk + r8);
            const __nv_bfloat16* pa = (const __nv_bfloat16*)&va;
            const __nv_bfloat16* pb = (const __nv_bfloat16*)&vb;
            const __nv_bfloat16* pc = (const __nv_bfloat16*)&vc;
            const __nv_bfloat16* pd = (const __nv_bfloat16*)&vd;
#pragma unroll
            for (int i = 0; i < 8; i++) {
                int sa = swz3(r8 + i, cp) + cb;
                sAh[sa] = pa[i];
                sAl[sa] = pb[i];
                sBh[sa] = pc[i];
                sBl[sa] = pd[i];
            }
        }
        __syncthreads();
#pragma unroll
        for (int s = 0; s < 2; s++) {
            int p0 = s * 8 + qi;          // c-pair index for this thread's k slice
            uint32_t ah[4][4], al[4][4];
#pragma unroll
            for (int mi = 0; mi < 4; mi++) {
                int m0 = wm * 64 + mi * 16 + g;
                ah[mi][0] = *(const uint32_t*)&sAh[swz3(m0, p0)];
                ah[mi][1] = *(const uint32_t*)&sAh[swz3(m0 + 8, p0)];
                ah[mi][2] = *(const uint32_t*)&sAh[swz3(m0, p0 + 4)];
                ah[mi][3] = *(const uint32_t*)&sAh[swz3(m0 + 8, p0 + 4)];
                al[mi][0] = *(const uint32_t*)&sAl[swz3(m0, p0)];
                al[mi][1] = *(const uint32_t*)&sAl[swz3(m0 + 8, p0)];
                al[mi][2] = *(const uint32_t*)&sAl[swz3(m0, p0 + 4)];
                al[mi][3] = *(const uint32_t*)&sAl[swz3(m0 + 8, p0 + 4)];
            }
            uint32_t bh[4][2], bl[4][2];
#pragma unroll
            for (int ni = 0; ni < 4; ni++) {
                int n0 = wn * 32 + ni * 8 + g;
                bh[ni][0] = *(const uint32_t*)&sBh[swz3(n0, p0)];
                bh[ni][1] = *(const uint32_t*)&sBh[swz3(n0, p0 + 4)];
                bl[ni][0] = *(const uint32_t*)&sBl[swz3(n0, p0)];
                bl[ni][1] = *(const uint32_t*)&sBl[swz3(n0, p0 + 4)];
            }
#pragma unroll
            for (int mi = 0; mi < 4; mi++)
#pragma unroll
                for (int ni = 0; ni < 4; ni++) {
                    MMA16816(acc[mi][ni], ah[mi], bh[ni]);
                    MMA16816(acc[mi][ni], al[mi], bh[ni]);
                    MMA16816(acc[mi][ni], ah[mi], bl[ni]);
                }
        }
        __syncthreads();
    }

    // epilogue: T[q][d], scale 1/colsum[q], fallback cmean[d]
#pragma unroll
    for (int ni = 0; ni < 4; ni++) {
        int d = dblk + wn * 32 + ni * 8 + qi * 2;
        float fb0 = g_cmean[b * Dd + d], fb1 = g_cmean[b * Dd + d + 1];
#pragma unroll
        for (int mi = 0; mi < 4; mi++) {
            int q0 = qblk + wm * 64 + mi * 16 + g;
            int q1 = q0 + 8;
            float cs0 = g_colsum[b * LQ + q0];
            float cs1 = g_colsum[b * LQ + q1];
            float2 v0, v1;
            if (cs0 > 0.f) { float iv = 1.0f / cs0; v0.x = acc[mi][ni][0] * iv; v0.y = acc[mi][ni][1] * iv; }
            else           { v0.x = fb0; v0.y = fb1; }
            if (cs1 > 0.f) { float iv = 1.0f / cs1; v1.x = acc[mi][ni][2] * iv; v1.y = acc[mi][ni][3] * iv; }
            else           { v1.x = fb0; v1.y = fb1; }
            *(float2*)(g_T + ((size_t)b * LQ + q0) * Dd + d) = v0;
            *(float2*)(g_T + ((size_t)b * LQ + q1) * Dd + d) = v1;
        }
    }
}

// ---------------- K3b: tmean = mean_q T ----------------
__global__ void k3b_tmean() {
    int b = blockIdx.x, d = threadIdx.x;
    const float* p = g_T + (size_t)b * LQ * Dd + d;
    float s0 = 0, s1 = 0, s2 = 0, s3 = 0;
    for (int q = 0; q < LQ; q += 4) {
        s0 += p[(size_t)(q + 0) * Dd]; s1 += p[(size_t)(q + 1) * Dd];
        s2 += p[(size_t)(q + 2) * Dd]; s3 += p[(size_t)(q + 3) * Dd];
    }
    g_tmean[b * Dd + d] = ((s0 + s1) + (s2 + s3)) * (1.0f / LQ);
}

// ---------------- K4 (HMMA): Out[c][d] = (1/rowsum[c]) * sum_q E[c][q] * Bsrc[q][d] ----
#define K4ST 40
__global__ __launch_bounds__(256)
void k4_mma(float* __restrict__ out) {
    __shared__ __nv_bfloat16 sEh[128 * K4ST];
    __shared__ __nv_bfloat16 sEl[128 * K4ST];
    __shared__ __nv_bfloat16 sQh[128 * K4ST];
    __shared__ __nv_bfloat16 sQl[128 * K4ST];

    int tid = threadIdx.x, wid = tid >> 5, lane = tid & 31;
    int b = blockIdx.z;
    int cblk = blockIdx.x * 128;
    int sel = blockIdx.y >> 1;
    int dblk = (blockIdx.y & 1) * 128;

    const __nv_bfloat16* Eh = g_Eh + ((size_t)b * LC + cblk) * LQ;
    const __nv_bfloat16* El = g_El + ((size_t)b * LC + cblk) * LQ;
    const __nv_bfloat16* Qh = (sel ? g_TTh : g_qTh) + ((size_t)b * Dd + dblk) * LQ;
    const __nv_bfloat16* Ql = (sel ? g_TTl : g_qTl) + ((size_t)b * Dd + dblk) * LQ;
    const float* fb = (sel ? g_tmean : g_qmean) + b * Dd;
    float* op = out + (size_t)sel * Bb * LC * Dd + (size_t)b * LC * Dd;

    int wm = wid & 1;
    int wn = wid >> 1;
    int g = lane >> 2;
    int qi = lane & 3;

    float acc[4][4][4];
#pragma unroll
    for (int mi = 0; mi < 4; mi++)
#pragma unroll
        for (int ni = 0; ni < 4; ni++)
#pragma unroll
            for (int r = 0; r < 4; r++) acc[mi][ni][r] = 0.f;

    for (int ko = 0; ko < LQ; ko += 32) {
#pragma unroll
        for (int j = 0; j < 2; j++) {
            int cid = tid * 2 + j;
            int row = cid >> 2;
            int c8 = (cid & 3) * 8;
            size_t go = (size_t)row * LQ + ko + c8;
            int so = row * K4ST + c8;
            *(uint4*)&sEh[so] = *(const uint4*)(Eh + go);
            *(uint4*)&sEl[so] = *(const uint4*)(El + go);
            *(uint4*)&sQh[so] = *(const uint4*)(Qh + go);
            *(uint4*)&sQl[so] = *(const uint4*)(Ql + go);
        }
        __syncthreads();

#pragma unroll
        for (int s = 0; s < 2; s++) {
            int kl = s * 16;
            uint32_t ah[4][4], al[4][4];
#pragma unroll
            for (int mi = 0; mi < 4; mi++) {
                int off = (wm * 64 + mi * 16 + g) * K4ST + kl + qi * 2;
                ah[mi][0] = *(const uint32_t*)&sEh[off];
                ah[mi][1] = *(const uint32_t*)&sEh[off + 8 * K4ST];
                ah[mi][2] = *(const uint32_t*)&sEh[off + 8];
                ah[mi][3] = *(const uint32_t*)&sEh[off + 8 * K4ST + 8];
                al[mi][0] = *(const uint32_t*)&sEl[off];
                al[mi][1] = *(const uint32_t*)&sEl[off + 8 * K4ST];
                al[mi][2] = *(const uint32_t*)&sEl[off + 8];
                al[mi][3] = *(const uint32_t*)&sEl[off + 8 * K4ST + 8];
            }
            uint32_t bh[4][2], bl[4][2];
#pragma unroll
            for (int ni = 0; ni < 4; ni++) {
                int off = (wn * 32 + ni * 8 + g) * K4ST + kl + qi * 2;
                bh[ni][0] = *(const uint32_t*)&sQh[off];
                bh[ni][1] = *(const uint32_t*)&sQh[off + 8];
                bl[ni][0] = *(const uint32_t*)&sQl[off];
                bl[ni][1] = *(const uint32_t*)&sQl[off + 8];
            }
#pragma unroll
            for (int mi = 0; mi < 4; mi++)
#pragma unroll
                for (int ni = 0; ni < 4; ni++) {
                    MMA16816(acc[mi][ni], ah[mi], bh[ni]);
                    MMA16816(acc[mi][ni], al[mi], bh[ni]);
                    MMA16816(acc[mi][ni], ah[mi], bl[ni]);
                }
        }
        __syncthreads();
    }

#pragma unroll
    for (int ni = 0; ni < 4; ni++) {
        int dcol = dblk + wn * 32 + ni * 8 + qi * 2;
        float fb0 = fb[dcol], fb1 = fb[dcol + 1];
#pragma unroll
        for (int mi = 0; mi < 4; mi++) {
            int c0 = cblk + wm * 64 + mi * 16 + g;
            int c1 = c0 + 8;
            float inv0 = g_invrow[b * LC + c0];
            float inv1 = g_invrow[b * LC + c1];
            float2 v0, v1;
            if (inv0 > 0.f) { v0.x = acc[mi][ni][0] * inv0; v0.y = acc[mi][ni][1] * inv0; }
            else            { v0.x = fb0; v0.y = fb1; }
            if (inv1 > 0.f) { v1.x = acc[mi][ni][2] * inv1; v1.y = acc[mi][ni][3] * inv1; }
            else            { v1.x = fb0; v1.y = fb1; }
            *(float2*)(op + (size_t)c0 * Dd + dcol) = v0;
            *(float2*)(op + (size_t)c1 * Dd + dcol) = v1;
        }
    }
}

// ---------------- launcher ----------------
extern "C" void kernel_launch(void* const* d_in, const int* in_sizes, int n_in,
                              void* d_out, int out_size) {
    const float* ctx = (const float*)d_in[0];
    const float* qry = (const float*)d_in[1];
    const void* cmask = d_in[2];
    const void* qmask = d_in[3];
    const float* w0 = (const float*)d_in[4];
    float* out = (float*)d_out;

    k_detect<<<1, 32>>>((const unsigned char*)cmask);
    k_cvt_mask<<<(Bb * LC + 255) / 256, 256>>>(cmask, qmask);
    k0_rowdots<<<(Bb * (LC + LQ)) / 8, 256>>>(ctx, qry, w0);
    k0_means<<<dim3(Bb, 9), 256>>>(ctx, qry);
    k_cvtC<<<(int)(((size_t)Bb * LC * Dd / 4) / 256), 256>>>(ctx);
    k_cvtQW<<<(int)(((size_t)Bb * LQ * Dd / 4) / 256), 256>>>(qry, w0);
    k_cvtQT<<<dim3(1, Dd, Bb), LQ>>>(qry);
    k1_mma<<<dim3(LC / 128, LQ / 128, Bb), 256>>>();
    k2_reduce<<<Bb, 256>>>();
    k3_mma<<<dim3(LQ / 128, Dd / 128, Bb), 256>>>();
    k3b_tmean<<<Bb, 256>>>();
    k_cvtTT<<<dim3(1, Dd, Bb), LQ>>>();
    k4_mma<<<dim3(LC / 128, 4, Bb), 256>>>(out);
}

// round 16
// speedup vs baseline: 1.9723x; 1.3137x over previous
#include <cuda_runtime.h>
#include <cuda_bf16.h>
#include <math.h>
#include <stdint.h>

// Problem dims
#define Bb 32
#define LC 2048
#define LQ 256
#define Dd 256

// ---------------- mma.sync helper (HMMA bf16, baseline PTX, works on sm_103) ----------
#define MMA16816(c, a, bq)                                                              \
    asm volatile(                                                                       \
        "mma.sync.aligned.m16n8k16.row.col.f32.bf16.bf16.f32 "                          \
        "{%0,%1,%2,%3}, {%4,%5,%6,%7}, {%8,%9}, {%0,%1,%2,%3};"                         \
        : "+f"((c)[0]), "+f"((c)[1]), "+f"((c)[2]), "+f"((c)[3])                        \
        : "r"((a)[0]), "r"((a)[1]), "r"((a)[2]), "r"((a)[3]),                           \
          "r"((bq)[0]), "r"((bq)[1]))

__device__ __forceinline__ void ldsm4(uint32_t* r, uint32_t a) {
    asm volatile("ldmatrix.sync.aligned.m8n8.x4.shared.b16 {%0,%1,%2,%3}, [%4];"
        : "=r"(r[0]), "=r"(r[1]), "=r"(r[2]), "=r"(r[3]) : "r"(a));
}
__device__ __forceinline__ void ldsm2(uint32_t* r, uint32_t a) {
    asm volatile("ldmatrix.sync.aligned.m8n8.x2.shared.b16 {%0,%1}, [%2];"
        : "=r"(r[0]), "=r"(r[1]) : "r"(a));
}
__device__ __forceinline__ void ldsm4t(uint32_t* r, uint32_t a) {
    asm volatile("ldmatrix.sync.aligned.m8n8.x4.trans.shared.b16 {%0,%1,%2,%3}, [%4];"
        : "=r"(r[0]), "=r"(r[1]), "=r"(r[2]), "=r"(r[3]) : "r"(a));
}
__device__ __forceinline__ void ldsm2t(uint32_t* r, uint32_t a) {
    asm volatile("ldmatrix.sync.aligned.m8n8.x2.trans.shared.b16 {%0,%1}, [%2];"
        : "=r"(r[0]), "=r"(r[1]) : "r"(a));
}
__device__ __forceinline__ void cp16(uint32_t s, const void* g) {
    asm volatile("cp.async.cg.shared.global [%0], [%1], 16;" :: "r"(s), "l"(g));
}
#define CP_COMMIT() asm volatile("cp.async.commit_group;" ::: "memory")
#define CP_WAIT1()  asm volatile("cp.async.wait_group 1;" ::: "memory")
#define CP_WAIT0()  asm volatile("cp.async.wait_group 0;" ::: "memory")

// ---------------- scratch (device globals; no allocations allowed) ----------------
__device__ float g_T[(size_t)Bb * LQ * Dd];          // T fp32                 (8 MB)
__device__ __nv_bfloat16 g_Eh[(size_t)Bb * LC * LQ]; // E hi split [c][q]      (32 MB)
__device__ __nv_bfloat16 g_El[(size_t)Bb * LC * LQ]; // E lo split             (32 MB)
__device__ __nv_bfloat16 g_ch[(size_t)Bb * LC * Dd]; // ctx hi split [c][d]    (32 MB)
__device__ __nv_bfloat16 g_cl[(size_t)Bb * LC * Dd];
__device__ __nv_bfloat16 g_qwh[(size_t)Bb * LQ * Dd];// (qry*wm) hi [q][d]      (4 MB)
__device__ __nv_bfloat16 g_qwl[(size_t)Bb * LQ * Dd];
__device__ __nv_bfloat16 g_qTh[(size_t)Bb * Dd * LQ];// query^T hi [d][q]       (4 MB)
__device__ __nv_bfloat16 g_qTl[(size_t)Bb * Dd * LQ];
__device__ __nv_bfloat16 g_TTh[(size_t)Bb * Dd * LQ];// T^T hi     [d][q]       (4 MB)
__device__ __nv_bfloat16 g_TTl[(size_t)Bb * Dd * LQ];
__device__ float g_sc[Bb * LC];
__device__ float g_sq[Bb * LQ];
__device__ float g_rowsum_part[Bb * 2 * LC];
__device__ float g_invrow[Bb * LC];
__device__ float g_colsum_part[Bb * 16 * LQ];
__device__ float g_colsum[Bb * LQ];
__device__ float g_qmean[Bb * Dd];
__device__ float g_cmean_part[Bb * 8 * Dd];
__device__ float g_cmean[Bb * Dd];
__device__ float g_tmean[Bb * Dd];
__device__ unsigned char g_cm[Bb * LC];
__device__ unsigned char g_qm[Bb * LQ];
__device__ int g_is32;

// ---------------- mask dtype detection + canonicalization ----------------
__global__ void k_detect(const unsigned char* __restrict__ cm) {
    if (threadIdx.x == 0 && blockIdx.x == 0) {
        int is32 = 1;
        for (int i = 0; i < 4096; i++) {
            if ((i & 3) && cm[i]) { is32 = 0; break; }
        }
        g_is32 = is32;
    }
}

__global__ void k_cvt_mask(const void* __restrict__ cm, const void* __restrict__ qm) {
    int i = blockIdx.x * 256 + threadIdx.x;
    int is32 = g_is32;
    if (i < Bb * LC) {
        g_cm[i] = is32 ? (unsigned char)(((const int*)cm)[i] != 0)
                       : (unsigned char)(((const unsigned char*)cm)[i] != 0);
    }
    if (i < Bb * LQ) {
        g_qm[i] = is32 ? (unsigned char)(((const int*)qm)[i] != 0)
                       : (unsigned char)(((const unsigned char*)qm)[i] != 0);
    }
}

// ---------------- K0a: sc = context @ wc, sq = query @ wq ----------------
__global__ void k0_rowdots(const float* __restrict__ ctx, const float* __restrict__ qry,
                           const float* __restrict__ w0) {
    int warp = (blockIdx.x * blockDim.x + threadIdx.x) >> 5;
    int lane = threadIdx.x & 31;
    const int nC = Bb * LC;
    const float* src;
    const float* wgt;
    float* dst;
    if (warp < nC) {
        src = ctx + (size_t)warp * Dd; wgt = w0; dst = g_sc + warp;
    } else {
        int r = warp - nC;
        if (r >= Bb * LQ) return;
        src = qry + (size_t)r * Dd; wgt = w0 + Dd; dst = g_sq + r;
    }
    float s = 0.f;
#pragma unroll
    for (int i = 0; i < 2; i++) {
        int idx = (lane + 32 * i) * 4;
        float4 v = *(const float4*)(src + idx);
        float4 w = *(const float4*)(wgt + idx);
        s += v.x * w.x + v.y * w.y + v.z * w.z + v.w * w.w;
    }
#pragma unroll
    for (int o = 16; o; o >>= 1) s += __shfl_xor_sync(0xffffffffu, s, o);
    if (lane == 0) *dst = s;
}

// ---------------- K0b: qmean, cmean partials ----------------
__global__ void k0_means(const float* __restrict__ ctx, const float* __restrict__ qry) {
    int b = blockIdx.x, y = blockIdx.y, d = threadIdx.x;
    if (y == 0) {
        const float* p = qry + (size_t)b * LQ * Dd + d;
        float s0 = 0, s1 = 0, s2 = 0, s3 = 0, s4 = 0, s5 = 0, s6 = 0, s7 = 0;
        for (int q = 0; q < LQ; q += 8) {
            s0 += p[(size_t)(q + 0) * Dd]; s1 += p[(size_t)(q + 1) * Dd];
            s2 += p[(size_t)(q + 2) * Dd]; s3 += p[(size_t)(q + 3) * Dd];
            s4 += p[(size_t)(q + 4) * Dd]; s5 += p[(size_t)(q + 5) * Dd];
            s6 += p[(size_t)(q + 6) * Dd]; s7 += p[(size_t)(q + 7) * Dd];
        }
        g_qmean[b * Dd + d] = (((s0 + s1) + (s2 + s3)) + ((s4 + s5) + (s6 + s7))) * (1.0f / LQ);
    } else {
        int chunk = y - 1;
        const float* p = ctx + ((size_t)b * LC + chunk * 256) * Dd + d;
        float s0 = 0, s1 = 0, s2 = 0, s3 = 0, s4 = 0, s5 = 0, s6 = 0, s7 = 0;
        for (int c = 0; c < 256; c += 8) {
            s0 += p[(size_t)(c + 0) * Dd]; s1 += p[(size_t)(c + 1) * Dd];
            s2 += p[(size_t)(c + 2) * Dd]; s3 += p[(size_t)(c + 3) * Dd];
            s4 += p[(size_t)(c + 4) * Dd]; s5 += p[(size_t)(c + 5) * Dd];
            s6 += p[(size_t)(c + 6) * Dd]; s7 += p[(size_t)(c + 7) * Dd];
        }
        g_cmean_part[((size_t)b * 8 + chunk) * Dd + d] =
            ((s0 + s1) + (s2 + s3)) + ((s4 + s5) + (s6 + s7));
    }
}

// ---------------- bf16 split conversions ----------------
__device__ __forceinline__ void split2(float x, float y, __nv_bfloat162& h, __nv_bfloat162& l) {
    __nv_bfloat16 hx = __float2bfloat16(x), hy = __float2bfloat16(y);
    h.x = hx; h.y = hy;
    l.x = __float2bfloat16(x - __bfloat162float(hx));
    l.y = __float2bfloat16(y - __bfloat162float(hy));
}

__global__ void k_cvtC(const float* __restrict__ ctx) {
    size_t i = ((size_t)blockIdx.x * 256 + threadIdx.x) * 4;
    float4 v = *(const float4*)(ctx + i);
    __nv_bfloat162 h0, l0, h1, l1;
    split2(v.x, v.y, h0, l0);
    split2(v.z, v.w, h1, l1);
    *(__nv_bfloat162*)(g_ch + i) = h0;     *(__nv_bfloat162*)(g_ch + i + 2) = h1;
    *(__nv_bfloat162*)(g_cl + i) = l0;     *(__nv_bfloat162*)(g_cl + i + 2) = l1;
}

__global__ void k_cvtQW(const float* __restrict__ qry, const float* __restrict__ w0) {
    size_t i = ((size_t)blockIdx.x * 256 + threadIdx.x) * 4;
    int d = (int)(i & (Dd - 1));
    float4 v = *(const float4*)(qry + i);
    float4 w = *(const float4*)(w0 + 2 * Dd + d);
    v.x *= w.x; v.y *= w.y; v.z *= w.z; v.w *= w.w;
    __nv_bfloat162 h0, l0, h1, l1;
    split2(v.x, v.y, h0, l0);
    split2(v.z, v.w, h1, l1);
    *(__nv_bfloat162*)(g_qwh + i) = h0;    *(__nv_bfloat162*)(g_qwh + i + 2) = h1;
    *(__nv_bfloat162*)(g_qwl + i) = l0;    *(__nv_bfloat162*)(g_qwl + i + 2) = l1;
}

__global__ void k_cvtQT(const float* __restrict__ qry) {
    int q = threadIdx.x, d = blockIdx.y, b = blockIdx.z;
    float v = qry[((size_t)b * LQ + q) * Dd + d];
    __nv_bfloat16 h = __float2bfloat16(v);
    __nv_bfloat16 l = __float2bfloat16(v - __bfloat162float(h));
    size_t o = ((size_t)b * Dd + d) * LQ + q;
    g_qTh[o] = h; g_qTl[o] = l;
}

__global__ void k_cvtTT() {
    int q = threadIdx.x, d = blockIdx.y, b = blockIdx.z;
    float v = g_T[((size_t)b * LQ + q) * Dd + d];
    __nv_bfloat16 h = __float2bfloat16(v);
    __nv_bfloat16 l = __float2bfloat16(v - __bfloat162float(h));
    size_t o = ((size_t)b * Dd + d) * LQ + q;
    g_TTh[o] = h; g_TTl[o] = l;
}

// ============================================================================
// K1 (HMMA + ldmatrix + cp.async pipeline)
// sim = ctx @ (qry*wm)^T + sc + sq;  E = exp(masked sim) -> bf16 split + partials
// A = ctx split [c][d], B = qw split [q][d]; m=128c, n=128q, k-chunks of 32.
// ============================================================================
#define ST 40
#define TILEB (128 * ST * 2)   // 10240 bytes per matrix per stage

__global__ __launch_bounds__(256, 2)
void k1_mma() {
    extern __shared__ __nv_bfloat16 dyn1[];
    __shared__ float s_rp[4][128];
    __shared__ float s_cp[2][128];
    uint32_t sb = (uint32_t)__cvta_generic_to_shared(dyn1);

    int tid = threadIdx.x, wid = tid >> 5, lane = tid & 31;
    int b = blockIdx.z;
    int cblk = blockIdx.x * 128;
    int qblk = blockIdx.y * 128;

    const __nv_bfloat16* Ah = g_ch + ((size_t)b * LC + cblk) * Dd;
    const __nv_bfloat16* Al = g_cl + ((size_t)b * LC + cblk) * Dd;
    const __nv_bfloat16* Bh = g_qwh + ((size_t)b * LQ + qblk) * Dd;
    const __nv_bfloat16* Bl = g_qwl + ((size_t)b * LQ + qblk) * Dd;

    int wm = wid & 1, wn = wid >> 1;
    int g = lane >> 2, qi = lane & 3;

    // ldmatrix per-lane address components
    int aR = (lane & 7) + (((lane >> 3) & 1) << 3);   // A x4 row
    int aC = (((lane >> 4) & 1) << 3);                // A x4 col sel
    int bR = lane & 7;                                // B x2 row
    int bC = (((lane >> 3) & 1) << 3);                // B x2 col sel

    float acc[4][4][4];
#pragma unroll
    for (int mi = 0; mi < 4; mi++)
#pragma unroll
        for (int ni = 0; ni < 4; ni++)
#pragma unroll
            for (int r = 0; r < 4; r++) acc[mi][ni][r] = 0.f;

#define K1_LOAD(ch, stg)                                                        \
    {                                                                           \
        int ko_ = (ch) * 32;                                                    \
        uint32_t sbase_ = sb + (stg) * 4 * TILEB;                               \
        _Pragma("unroll")                                                       \
        for (int j = 0; j < 2; j++) {                                           \
            int cid = tid * 2 + j;                                              \
            int row = cid >> 2, c8 = (cid & 3) * 8;                             \
            size_t go = (size_t)row * Dd + ko_ + c8;                            \
            uint32_t so = sbase_ + (row * ST + c8) * 2;                         \
            cp16(so, Ah + go);                                                  \
            cp16(so + TILEB, Al + go);                                          \
            cp16(so + 2 * TILEB, Bh + go);                                      \
            cp16(so + 3 * TILEB, Bl + go);                                      \
        }                                                                       \
        CP_COMMIT();                                                            \
    }

    K1_LOAD(0, 0)
    for (int ch = 0; ch < 8; ch++) {
        if (ch < 7) { K1_LOAD(ch + 1, (ch + 1) & 1) CP_WAIT1(); }
        else CP_WAIT0();
        __syncthreads();
        uint32_t base = sb + (ch & 1) * 4 * TILEB;
#pragma unroll
        for (int s = 0; s < 2; s++) {
            int kl = s * 16;
            uint32_t bh[4][2], bl[4][2];
#pragma unroll
            for (int ni = 0; ni < 4; ni++) {
                uint32_t off = ((wn * 32 + ni * 8 + bR) * ST + kl + bC) * 2;
                ldsm2(bh[ni], base + 2 * TILEB + off);
                ldsm2(bl[ni], base + 3 * TILEB + off);
            }
#pragma unroll
            for (int mi = 0; mi < 4; mi++) {
                uint32_t off = ((wm * 64 + mi * 16 + aR) * ST + kl + aC) * 2;
                uint32_t ah[4], al[4];
                ldsm4(ah, base + off);
                ldsm4(al, base + TILEB + off);
#pragma unroll
                for (int ni = 0; ni < 4; ni++) {
                    MMA16816(acc[mi][ni], ah, bh[ni]);
                    MMA16816(acc[mi][ni], al, bh[ni]);
                    MMA16816(acc[mi][ni], ah, bl[ni]);
                }
            }
        }
        __syncthreads();
    }

    // ---- epilogue: sim -> E, splits, partial sums ----
    float scv[4][2]; int cmv[4][2]; int crow[4][2];
#pragma unroll
    for (int mi = 0; mi < 4; mi++)
#pragma unroll
        for (int h = 0; h < 2; h++) {
            int c = cblk + wm * 64 + mi * 16 + g + h * 8;
            crow[mi][h] = c;
            scv[mi][h] = g_sc[b * LC + c];
            cmv[mi][h] = g_cm[b * LC + c];
        }
    float sqv[4][2]; int qmv[4][2]; int qcol[4];
#pragma unroll
    for (int ni = 0; ni < 4; ni++) {
        int q = qblk + wn * 32 + ni * 8 + qi * 2;
        qcol[ni] = q;
        sqv[ni][0] = g_sq[b * LQ + q];     qmv[ni][0] = g_qm[b * LQ + q];
        sqv[ni][1] = g_sq[b * LQ + q + 1]; qmv[ni][1] = g_qm[b * LQ + q + 1];
    }

    float rowp[4][2]; float colp[4][2];
#pragma unroll
    for (int i = 0; i < 4; i++) { rowp[i][0] = rowp[i][1] = colp[i][0] = colp[i][1] = 0.f; }

#pragma unroll
    for (int mi = 0; mi < 4; mi++)
#pragma unroll
        for (int ni = 0; ni < 4; ni++) {
            float e[4];
#pragma unroll
            for (int r = 0; r < 4; r++) {
                int h = r >> 1, jj = r & 1;
                float sv = acc[mi][ni][r] + scv[mi][h] + sqv[ni][jj];
                e[r] = (cmv[mi][h] | qmv[ni][jj]) ? 0.f : __expf(sv);
            }
            rowp[mi][0] += e[0] + e[1];
            rowp[mi][1] += e[2] + e[3];
            colp[ni][0] += e[0] + e[2];
            colp[ni][1] += e[1] + e[3];
#pragma unroll
            for (int h = 0; h < 2; h++) {
                __nv_bfloat162 hh, ll;
                split2(e[h * 2], e[h * 2 + 1], hh, ll);
                size_t idx = (size_t)(b * LC + crow[mi][h]) * LQ + qcol[ni];
                *(__nv_bfloat162*)(g_Eh + idx) = hh;
                *(__nv_bfloat162*)(g_El + idx) = ll;
            }
        }

#pragma unroll
    for (int mi = 0; mi < 4; mi++)
#pragma unroll
        for (int h = 0; h < 2; h++) {
            float v = rowp[mi][h];
            v += __shfl_xor_sync(0xffffffffu, v, 1);
            v += __shfl_xor_sync(0xffffffffu, v, 2);
            if (qi == 0) s_rp[wn][wm * 64 + mi * 16 + g + h * 8] = v;
        }
#pragma unroll
    for (int ni = 0; ni < 4; ni++)
#pragma unroll
        for (int jj = 0; jj < 2; jj++) {
            float v = colp[ni][jj];
            v += __shfl_xor_sync(0xffffffffu, v, 4);
            v += __shfl_xor_sync(0xffffffffu, v, 8);
            v += __shfl_xor_sync(0xffffffffu, v, 16);
            if (lane < 4) s_cp[wm][wn * 32 + ni * 8 + qi * 2 + jj] = v;
        }
    __syncthreads();
    if (tid < 128) {
        float r = s_rp[0][tid] + s_rp[1][tid] + s_rp[2][tid] + s_rp[3][tid];
        g_rowsum_part[((size_t)b * 2 + blockIdx.y) * LC + cblk + tid] = r;
        float cs = s_cp[0][tid] + s_cp[1][tid];
        g_colsum_part[((size_t)b * 16 + blockIdx.x) * LQ + qblk + tid] = cs;
    }
}

// ---------------- K2: deterministic partial reductions ----------------
__global__ void k2_reduce() {
    int b = blockIdx.x, tid = threadIdx.x;
    for (int c = tid; c < LC; c += 256) {
        float rs = g_rowsum_part[((size_t)b * 2 + 0) * LC + c] +
                   g_rowsum_part[((size_t)b * 2 + 1) * LC + c];
        g_invrow[b * LC + c] = rs > 0.f ? 1.0f / rs : 0.f;
    }
    {
        int q = tid;
        float s = 0.f;
#pragma unroll
        for (int t = 0; t < 16; t++) s += g_colsum_part[((size_t)b * 16 + t) * LQ + q];
        g_colsum[b * LQ + q] = s;
    }
    {
        int d = tid;
        float s = 0.f;
#pragma unroll
        for (int t = 0; t < 8; t++) s += g_cmean_part[((size_t)b * 8 + t) * Dd + d];
        g_cmean[b * Dd + d] = s * (1.0f / LC);
    }
}

// ============================================================================
// K3 (HMMA + trans-ldmatrix + cp.async pipeline)
// T[q][d] = (1/colsum[q]) * sum_c E[c][q]*ctx[c][d]
// smem tiles stored untransposed ([c][q] / [c][d]); ldmatrix.trans makes fragments.
// ============================================================================
#define ST3 136
#define TILE3B (32 * ST3 * 2)   // 8704 bytes per matrix per stage

__global__ __launch_bounds__(256, 2)
void k3_mma() {
    extern __shared__ __nv_bfloat16 dyn3[];
    uint32_t sb = (uint32_t)__cvta_generic_to_shared(dyn3);

    int tid = threadIdx.x, wid = tid >> 5, lane = tid & 31;
    int b = blockIdx.z;
    int qblk = blockIdx.x * 128;   // m (q)
    int dblk = blockIdx.y * 128;   // n (d)

    const __nv_bfloat16* Eh = g_Eh + (size_t)b * LC * LQ;
    const __nv_bfloat16* El = g_El + (size_t)b * LC * LQ;
    const __nv_bfloat16* Ch = g_ch + (size_t)b * LC * Dd;
    const __nv_bfloat16* Cl = g_cl + (size_t)b * LC * Dd;

    int wm = wid & 1, wn = wid >> 1;
    int g = lane >> 2, qi = lane & 3;

    // trans ldmatrix per-lane address components
    int aKr = (lane & 7) + (((lane >> 4) & 1) << 3);  // A x4 trans: k-row
    int aMc = (((lane >> 3) & 1) << 3);               // A x4 trans: m-col sel
    int bKr = lane & 15;                              // B x2 trans: k-row

    float acc[4][4][4];
#pragma unroll
    for (int mi = 0; mi < 4; mi++)
#pragma unroll
        for (int ni = 0; ni < 4; ni++)
#pragma unroll
            for (int r = 0; r < 4; r++) acc[mi][ni][r] = 0.f;

#define K3_LOAD(ch, stg)                                                        \
    {                                                                           \
        int ko_ = (ch) * 32;                                                    \
        uint32_t sbase_ = sb + (stg) * 4 * TILE3B;                              \
        _Pragma("unroll")                                                       \
        for (int j = 0; j < 2; j++) {                                           \
            int cid = tid * 2 + j;                                              \
            int row = cid >> 4, c8 = (cid & 15) * 8;                            \
            uint32_t so = sbase_ + (row * ST3 + c8) * 2;                        \
            size_t gq = (size_t)(ko_ + row) * LQ + qblk + c8;                   \
            size_t gd = (size_t)(ko_ + row) * Dd + dblk + c8;                   \
            cp16(so, Eh + gq);                                                  \
            cp16(so + TILE3B, El + gq);                                         \
            cp16(so + 2 * TILE3B, Ch + gd);                                     \
            cp16(so + 3 * TILE3B, Cl + gd);                                     \
        }                                                                       \
        CP_COMMIT();                                                            \
    }

    K3_LOAD(0, 0)
    for (int ch = 0; ch < 64; ch++) {
        if (ch < 63) { K3_LOAD(ch + 1, (ch + 1) & 1) CP_WAIT1(); }
        else CP_WAIT0();
        __syncthreads();
        uint32_t base = sb + (ch & 1) * 4 * TILE3B;
#pragma unroll
        for (int s = 0; s < 2; s++) {
            int kl = s * 16;
            uint32_t bh[4][2], bl[4][2];
#pragma unroll
            for (int ni = 0; ni < 4; ni++) {
                uint32_t off = ((kl + bKr) * ST3 + wn * 32 + ni * 8) * 2;
                ldsm2t(bh[ni], base + 2 * TILE3B + off);
                ldsm2t(bl[ni], base + 3 * TILE3B + off);
            }
#pragma unroll
            for (int mi = 0; mi < 4; mi++) {
                uint32_t off = ((kl + aKr) * ST3 + wm * 64 + mi * 16 + aMc) * 2;
                uint32_t ah[4], al[4];
                ldsm4t(ah, base + off);
                ldsm4t(al, base + TILE3B + off);
#pragma unroll
                for (int ni = 0; ni < 4; ni++) {
                    MMA16816(acc[mi][ni], ah, bh[ni]);
                    MMA16816(acc[mi][ni], al, bh[ni]);
                    MMA16816(acc[mi][ni], ah, bl[ni]);
                }
            }
        }
        __syncthreads();
    }

    // epilogue: T[q][d], scale 1/colsum[q], fallback cmean[d]
#pragma unroll
    for (int ni = 0; ni < 4; ni++) {
        int d = dblk + wn * 32 + ni * 8 + qi * 2;
        float fb0 = g_cmean[b * Dd + d], fb1 = g_cmean[b * Dd + d + 1];
#pragma unroll
        for (int mi = 0; mi < 4; mi++) {
            int q0 = qblk + wm * 64 + mi * 16 + g;
            int q1 = q0 + 8;
            float cs0 = g_colsum[b * LQ + q0];
            float cs1 = g_colsum[b * LQ + q1];
            float2 v0, v1;
            if (cs0 > 0.f) { float iv = 1.0f / cs0; v0.x = acc[mi][ni][0] * iv; v0.y = acc[mi][ni][1] * iv; }
            else           { v0.x = fb0; v0.y = fb1; }
            if (cs1 > 0.f) { float iv = 1.0f / cs1; v1.x = acc[mi][ni][2] * iv; v1.y = acc[mi][ni][3] * iv; }
            else           { v1.x = fb0; v1.y = fb1; }
            *(float2*)(g_T + ((size_t)b * LQ + q0) * Dd + d) = v0;
            *(float2*)(g_T + ((size_t)b * LQ + q1) * Dd + d) = v1;
        }
    }
}

// ---------------- K3b: tmean = mean_q T ----------------
__global__ void k3b_tmean() {
    int b = blockIdx.x, d = threadIdx.x;
    const float* p = g_T + (size_t)b * LQ * Dd + d;
    float s0 = 0, s1 = 0, s2 = 0, s3 = 0;
    for (int q = 0; q < LQ; q += 4) {
        s0 += p[(size_t)(q + 0) * Dd]; s1 += p[(size_t)(q + 1) * Dd];
        s2 += p[(size_t)(q + 2) * Dd]; s3 += p[(size_t)(q + 3) * Dd];
    }
    g_tmean[b * Dd + d] = ((s0 + s1) + (s2 + s3)) * (1.0f / LQ);
}

// ============================================================================
// K4 (HMMA + ldmatrix + cp.async pipeline)
// Out[c][d] = (1/rowsum[c]) * sum_q E[c][q] * Bsrc[q][d]
// ============================================================================
__global__ __launch_bounds__(256, 2)
void k4_mma(float* __restrict__ out) {
    extern __shared__ __nv_bfloat16 dyn4[];
    uint32_t sb = (uint32_t)__cvta_generic_to_shared(dyn4);

    int tid = threadIdx.x, wid = tid >> 5, lane = tid & 31;
    int b = blockIdx.z;
    int cblk = blockIdx.x * 128;
    int sel = blockIdx.y >> 1;
    int dblk = (blockIdx.y & 1) * 128;

    const __nv_bfloat16* Eh = g_Eh + ((size_t)b * LC + cblk) * LQ;
    const __nv_bfloat16* El = g_El + ((size_t)b * LC + cblk) * LQ;
    const __nv_bfloat16* Qh = (sel ? g_TTh : g_qTh) + ((size_t)b * Dd + dblk) * LQ;
    const __nv_bfloat16* Ql = (sel ? g_TTl : g_qTl) + ((size_t)b * Dd + dblk) * LQ;
    const float* fb = (sel ? g_tmean : g_qmean) + b * Dd;
    float* op = out + (size_t)sel * Bb * LC * Dd + (size_t)b * LC * Dd;

    int wm = wid & 1, wn = wid >> 1;
    int g = lane >> 2, qi = lane & 3;

    int aR = (lane & 7) + (((lane >> 3) & 1) << 3);
    int aC = (((lane >> 4) & 1) << 3);
    int bR = lane & 7;
    int bC = (((lane >> 3) & 1) << 3);

    float acc[4][4][4];
#pragma unroll
    for (int mi = 0; mi < 4; mi++)
#pragma unroll
        for (int ni = 0; ni < 4; ni++)
#pragma unroll
            for (int r = 0; r < 4; r++) acc[mi][ni][r] = 0.f;

#define K4_LOAD(ch, stg)                                                        \
    {                                                                           \
        int ko_ = (ch) * 32;                                                    \
        uint32_t sbase_ = sb + (stg) * 4 * TILEB;                               \
        _Pragma("unroll")                                                       \
        for (int j = 0; j < 2; j++) {                                           \
            int cid = tid * 2 + j;                                              \
            int row = cid >> 2, c8 = (cid & 3) * 8;                             \
            size_t go = (size_t)row * LQ + ko_ + c8;                            \
            uint32_t so = sbase_ + (row * ST + c8) * 2;                         \
            cp16(so, Eh + go);                                                  \
            cp16(so + TILEB, El + go);                                          \
            cp16(so + 2 * TILEB, Qh + go);                                      \
            cp16(so + 3 * TILEB, Ql + go);                                      \
        }                                                                       \
        CP_COMMIT();                                                            \
    }

    K4_LOAD(0, 0)
    for (int ch = 0; ch < 8; ch++) {
        if (ch < 7) { K4_LOAD(ch + 1, (ch + 1) & 1) CP_WAIT1(); }
        else CP_WAIT0();
        __syncthreads();
        uint32_t base = sb + (ch & 1) * 4 * TILEB;
#pragma unroll
        for (int s = 0; s < 2; s++) {
            int kl = s * 16;
            uint32_t bh[4][2], bl[4][2];
#pragma unroll
            for (int ni = 0; ni < 4; ni++) {
                uint32_t off = ((wn * 32 + ni * 8 + bR) * ST + kl + bC) * 2;
                ldsm2(bh[ni], base + 2 * TILEB + off);
                ldsm2(bl[ni], base + 3 * TILEB + off);
            }
#pragma unroll
            for (int mi = 0; mi < 4; mi++) {
                uint32_t off = ((wm * 64 + mi * 16 + aR) * ST + kl + aC) * 2;
                uint32_t ah[4], al[4];
                ldsm4(ah, base + off);
                ldsm4(al, base + TILEB + off);
#pragma unroll
                for (int ni = 0; ni < 4; ni++) {
                    MMA16816(acc[mi][ni], ah, bh[ni]);
                    MMA16816(acc[mi][ni], al, bh[ni]);
                    MMA16816(acc[mi][ni], ah, bl[ni]);
                }
            }
        }
        __syncthreads();
    }

#pragma unroll
    for (int ni = 0; ni < 4; ni++) {
        int dcol = dblk + wn * 32 + ni * 8 + qi * 2;
        float fb0 = fb[dcol], fb1 = fb[dcol + 1];
#pragma unroll
        for (int mi = 0; mi < 4; mi++) {
            int c0 = cblk + wm * 64 + mi * 16 + g;
            int c1 = c0 + 8;
            float inv0 = g_invrow[b * LC + c0];
            float inv1 = g_invrow[b * LC + c1];
            float2 v0, v1;
            if (inv0 > 0.f) { v0.x = acc[mi][ni][0] * inv0; v0.y = acc[mi][ni][1] * inv0; }
            else            { v0.x = fb0; v0.y = fb1; }
            if (inv1 > 0.f) { v1.x = acc[mi][ni][2] * inv1; v1.y = acc[mi][ni][3] * inv1; }
            else            { v1.x = fb0; v1.y = fb1; }
            *(float2*)(op + (size_t)c0 * Dd + dcol) = v0;
            *(float2*)(op + (size_t)c1 * Dd + dcol) = v1;
        }
    }
}

// ---------------- launcher ----------------
extern "C" void kernel_launch(void* const* d_in, const int* in_sizes, int n_in,
                              void* d_out, int out_size) {
    const float* ctx = (const float*)d_in[0];
    const float* qry = (const float*)d_in[1];
    const void* cmask = d_in[2];
    const void* qmask = d_in[3];
    const float* w0 = (const float*)d_in[4];
    float* out = (float*)d_out;

    const int smem1 = 2 * 4 * TILEB;    // 81920
    const int smem3 = 2 * 4 * TILE3B;   // 69632
    cudaFuncSetAttribute(k1_mma, cudaFuncAttributeMaxDynamicSharedMemorySize, smem1);
    cudaFuncSetAttribute(k3_mma, cudaFuncAttributeMaxDynamicSharedMemorySize, smem3);
    cudaFuncSetAttribute(k4_mma, cudaFuncAttributeMaxDynamicSharedMemorySize, smem1);

    k_detect<<<1, 32>>>((const unsigned char*)cmask);
    k_cvt_mask<<<(Bb * LC + 255) / 256, 256>>>(cmask, qmask);
    k0_rowdots<<<(Bb * (LC + LQ)) / 8, 256>>>(ctx, qry, w0);
    k0_means<<<dim3(Bb, 9), 256>>>(ctx, qry);
    k_cvtC<<<(int)(((size_t)Bb * LC * Dd / 4) / 256), 256>>>(ctx);
    k_cvtQW<<<(int)(((size_t)Bb * LQ * Dd / 4) / 256), 256>>>(qry, w0);
    k_cvtQT<<<dim3(1, Dd, Bb), LQ>>>(qry);
    k1_mma<<<dim3(LC / 128, LQ / 128, Bb), 256, smem1>>>();
    k2_reduce<<<Bb, 256>>>();
    k3_mma<<<dim3(LQ / 128, Dd / 128, Bb), 256, smem3>>>();
    k3b_tmean<<<Bb, 256>>>();
    k_cvtTT<<<dim3(1, Dd, Bb), LQ>>>();
    k4_mma<<<dim3(LC / 128, 4, Bb), 256, smem1>>>(out);
}

// round 17
// speedup vs baseline: 2.0097x; 1.0189x over previous
#include <cuda_runtime.h>
#include <cuda_bf16.h>
#include <math.h>
#include <stdint.h>

// Problem dims
#define Bb 32
#define LC 2048
#define LQ 256
#define Dd 256

// ---------------- mma.sync helper (HMMA bf16, baseline PTX, works on sm_103) ----------
#define MMA16816(c, a, bq)                                                              \
    asm volatile(                                                                       \
        "mma.sync.aligned.m16n8k16.row.col.f32.bf16.bf16.f32 "                          \
        "{%0,%1,%2,%3}, {%4,%5,%6,%7}, {%8,%9}, {%0,%1,%2,%3};"                         \
        : "+f"((c)[0]), "+f"((c)[1]), "+f"((c)[2]), "+f"((c)[3])                        \
        : "r"((a)[0]), "r"((a)[1]), "r"((a)[2]), "r"((a)[3]),                           \
          "r"((bq)[0]), "r"((bq)[1]))

__device__ __forceinline__ void ldsm4(uint32_t* r, uint32_t a) {
    asm volatile("ldmatrix.sync.aligned.m8n8.x4.shared.b16 {%0,%1,%2,%3}, [%4];"
        : "=r"(r[0]), "=r"(r[1]), "=r"(r[2]), "=r"(r[3]) : "r"(a));
}
__device__ __forceinline__ void ldsm2(uint32_t* r, uint32_t a) {
    asm volatile("ldmatrix.sync.aligned.m8n8.x2.shared.b16 {%0,%1}, [%2];"
        : "=r"(r[0]), "=r"(r[1]) : "r"(a));
}
__device__ __forceinline__ void ldsm4t(uint32_t* r, uint32_t a) {
    asm volatile("ldmatrix.sync.aligned.m8n8.x4.trans.shared.b16 {%0,%1,%2,%3}, [%4];"
        : "=r"(r[0]), "=r"(r[1]), "=r"(r[2]), "=r"(r[3]) : "r"(a));
}
__device__ __forceinline__ void ldsm2t(uint32_t* r, uint32_t a) {
    asm volatile("ldmatrix.sync.aligned.m8n8.x2.trans.shared.b16 {%0,%1}, [%2];"
        : "=r"(r[0]), "=r"(r[1]) : "r"(a));
}
__device__ __forceinline__ void cp16(uint32_t s, const void* g) {
    asm volatile("cp.async.cg.shared.global [%0], [%1], 16;" :: "r"(s), "l"(g));
}
#define CP_COMMIT() asm volatile("cp.async.commit_group;" ::: "memory")
#define CP_WAIT1()  asm volatile("cp.async.wait_group 1;" ::: "memory")
#define CP_WAIT0()  asm volatile("cp.async.wait_group 0;" ::: "memory")

// ---------------- scratch (device globals; no allocations allowed) ----------------
__device__ float g_T[(size_t)Bb * LQ * Dd];            // T fp32                 (8 MB)
__device__ float g_Tpart[(size_t)4 * Bb * LQ * Dd];    // K3 split-k partials   (32 MB)
__device__ __nv_bfloat16 g_Eh[(size_t)Bb * LC * LQ];   // E hi split [c][q]     (32 MB)
__device__ __nv_bfloat16 g_El[(size_t)Bb * LC * LQ];   // E lo split            (32 MB)
__device__ __nv_bfloat16 g_ch[(size_t)Bb * LC * Dd];   // ctx hi split [c][d]   (32 MB)
__device__ __nv_bfloat16 g_cl[(size_t)Bb * LC * Dd];
__device__ __nv_bfloat16 g_qwh[(size_t)Bb * LQ * Dd];  // (qry*wm) hi [q][d]     (4 MB)
__device__ __nv_bfloat16 g_qwl[(size_t)Bb * LQ * Dd];
__device__ __nv_bfloat16 g_qh[(size_t)Bb * LQ * Dd];   // qry hi [q][d]          (4 MB)
__device__ __nv_bfloat16 g_ql[(size_t)Bb * LQ * Dd];
__device__ __nv_bfloat16 g_Th[(size_t)Bb * LQ * Dd];   // T hi [q][d]            (4 MB)
__device__ __nv_bfloat16 g_Tl[(size_t)Bb * LQ * Dd];
__device__ float g_sc[Bb * LC];
__device__ float g_sq[Bb * LQ];
__device__ float g_rowsum_part[Bb * 2 * LC];
__device__ float g_invrow[Bb * LC];
__device__ float g_colsum_part[Bb * 16 * LQ];
__device__ float g_colsum[Bb * LQ];
__device__ float g_qmean[Bb * Dd];
__device__ float g_cmean_part[Bb * 8 * Dd];
__device__ float g_cmean[Bb * Dd];
__device__ float g_tmean[Bb * Dd];
__device__ unsigned char g_cm[Bb * LC];
__device__ unsigned char g_qm[Bb * LQ];
__device__ int g_is32;

// ---------------- mask dtype detection + canonicalization ----------------
__global__ void k_detect(const unsigned char* __restrict__ cm) {
    if (threadIdx.x == 0 && blockIdx.x == 0) {
        int is32 = 1;
        for (int i = 0; i < 4096; i++) {
            if ((i & 3) && cm[i]) { is32 = 0; break; }
        }
        g_is32 = is32;
    }
}

__global__ void k_cvt_mask(const void* __restrict__ cm, const void* __restrict__ qm) {
    int i = blockIdx.x * 256 + threadIdx.x;
    int is32 = g_is32;
    if (i < Bb * LC) {
        g_cm[i] = is32 ? (unsigned char)(((const int*)cm)[i] != 0)
                       : (unsigned char)(((const unsigned char*)cm)[i] != 0);
    }
    if (i < Bb * LQ) {
        g_qm[i] = is32 ? (unsigned char)(((const int*)qm)[i] != 0)
                       : (unsigned char)(((const unsigned char*)qm)[i] != 0);
    }
}

// ---------------- K0a: sc = context @ wc, sq = query @ wq ----------------
__global__ void k0_rowdots(const float* __restrict__ ctx, const float* __restrict__ qry,
                           const float* __restrict__ w0) {
    int warp = (blockIdx.x * blockDim.x + threadIdx.x) >> 5;
    int lane = threadIdx.x & 31;
    const int nC = Bb * LC;
    const float* src;
    const float* wgt;
    float* dst;
    if (warp < nC) {
        src = ctx + (size_t)warp * Dd; wgt = w0; dst = g_sc + warp;
    } else {
        int r = warp - nC;
        if (r >= Bb * LQ) return;
        src = qry + (size_t)r * Dd; wgt = w0 + Dd; dst = g_sq + r;
    }
    float s = 0.f;
#pragma unroll
    for (int i = 0; i < 2; i++) {
        int idx = (lane + 32 * i) * 4;
        float4 v = *(const float4*)(src + idx);
        float4 w = *(const float4*)(wgt + idx);
        s += v.x * w.x + v.y * w.y + v.z * w.z + v.w * w.w;
    }
#pragma unroll
    for (int o = 16; o; o >>= 1) s += __shfl_xor_sync(0xffffffffu, s, o);
    if (lane == 0) *dst = s;
}

// ---------------- split helpers ----------------
__device__ __forceinline__ void split2(float x, float y, __nv_bfloat162& h, __nv_bfloat162& l) {
    __nv_bfloat16 hx = __float2bfloat16(x), hy = __float2bfloat16(y);
    h.x = hx; h.y = hy;
    l.x = __float2bfloat16(x - __bfloat162float(hx));
    l.y = __float2bfloat16(y - __bfloat162float(hy));
}

// ---------------- K0b: fused ctx column-sums + bf16 split (one pass over ctx) ----------
__global__ void k0_ctx(const float* __restrict__ ctx) {
    int b = blockIdx.x, chunk = blockIdx.y, d = threadIdx.x;   // 256 threads = D
    size_t base = ((size_t)b * LC + chunk * 256) * Dd + d;
    const float* p = ctx + base;
    float s = 0.f;
#pragma unroll 4
    for (int c = 0; c < 256; c++) {
        float v = p[(size_t)c * Dd];
        s += v;
        __nv_bfloat16 h = __float2bfloat16(v);
        g_ch[base + (size_t)c * Dd] = h;
        g_cl[base + (size_t)c * Dd] = __float2bfloat16(v - __bfloat162float(h));
    }
    g_cmean_part[((size_t)b * 8 + chunk) * Dd + d] = s;
}

// ---------------- K0c: qmean ----------------
__global__ void k0_qmean(const float* __restrict__ qry) {
    int b = blockIdx.x, d = threadIdx.x;
    const float* p = qry + (size_t)b * LQ * Dd + d;
    float s0 = 0, s1 = 0, s2 = 0, s3 = 0;
    for (int q = 0; q < LQ; q += 4) {
        s0 += p[(size_t)(q + 0) * Dd]; s1 += p[(size_t)(q + 1) * Dd];
        s2 += p[(size_t)(q + 2) * Dd]; s3 += p[(size_t)(q + 3) * Dd];
    }
    g_qmean[b * Dd + d] = ((s0 + s1) + (s2 + s3)) * (1.0f / LQ);
}

// ---------------- k_cvtQW: one pass over query -> qw splits AND plain q splits --------
__global__ void k_cvtQW(const float* __restrict__ qry, const float* __restrict__ w0) {
    size_t i = ((size_t)blockIdx.x * 256 + threadIdx.x) * 4;
    int d = (int)(i & (Dd - 1));
    float4 v = *(const float4*)(qry + i);
    __nv_bfloat162 h0, l0, h1, l1;
    split2(v.x, v.y, h0, l0);
    split2(v.z, v.w, h1, l1);
    *(__nv_bfloat162*)(g_qh + i) = h0;     *(__nv_bfloat162*)(g_qh + i + 2) = h1;
    *(__nv_bfloat162*)(g_ql + i) = l0;     *(__nv_bfloat162*)(g_ql + i + 2) = l1;
    float4 w = *(const float4*)(w0 + 2 * Dd + d);
    v.x *= w.x; v.y *= w.y; v.z *= w.z; v.w *= w.w;
    split2(v.x, v.y, h0, l0);
    split2(v.z, v.w, h1, l1);
    *(__nv_bfloat162*)(g_qwh + i) = h0;    *(__nv_bfloat162*)(g_qwh + i + 2) = h1;
    *(__nv_bfloat162*)(g_qwl + i) = l0;    *(__nv_bfloat162*)(g_qwl + i + 2) = l1;
}

// ============================================================================
// K1 (HMMA + ldmatrix + cp.async pipeline)
// ============================================================================
#define ST 40
#define TILEB (128 * ST * 2)   // 10240 bytes per matrix per stage
#define ST3 136
#define TILE3B (32 * ST3 * 2)  // 8704 bytes per matrix per stage

__global__ __launch_bounds__(256, 2)
void k1_mma() {
    extern __shared__ __nv_bfloat16 dyn1[];
    __shared__ float s_rp[4][128];
    __shared__ float s_cp[2][128];
    uint32_t sb = (uint32_t)__cvta_generic_to_shared(dyn1);

    int tid = threadIdx.x, wid = tid >> 5, lane = tid & 31;
    int b = blockIdx.z;
    int cblk = blockIdx.x * 128;
    int qblk = blockIdx.y * 128;

    const __nv_bfloat16* Ah = g_ch + ((size_t)b * LC + cblk) * Dd;
    const __nv_bfloat16* Al = g_cl + ((size_t)b * LC + cblk) * Dd;
    const __nv_bfloat16* Bh = g_qwh + ((size_t)b * LQ + qblk) * Dd;
    const __nv_bfloat16* Bl = g_qwl + ((size_t)b * LQ + qblk) * Dd;

    int wm = wid & 1, wn = wid >> 1;
    int g = lane >> 2, qi = lane & 3;

    int aR = (lane & 7) + (((lane >> 3) & 1) << 3);
    int aC = (((lane >> 4) & 1) << 3);
    int bR = lane & 7;
    int bC = (((lane >> 3) & 1) << 3);

    float acc[4][4][4];
#pragma unroll
    for (int mi = 0; mi < 4; mi++)
#pragma unroll
        for (int ni = 0; ni < 4; ni++)
#pragma unroll
            for (int r = 0; r < 4; r++) acc[mi][ni][r] = 0.f;

#define K1_LOAD(ch, stg)                                                        \
    {                                                                           \
        int ko_ = (ch) * 32;                                                    \
        uint32_t sbase_ = sb + (stg) * 4 * TILEB;                               \
        _Pragma("unroll")                                                       \
        for (int j = 0; j < 2; j++) {                                           \
            int cid = tid * 2 + j;                                              \
            int row = cid >> 2, c8 = (cid & 3) * 8;                             \
            size_t go = (size_t)row * Dd + ko_ + c8;                            \
            uint32_t so = sbase_ + (row * ST + c8) * 2;                         \
            cp16(so, Ah + go);                                                  \
            cp16(so + TILEB, Al + go);                                          \
            cp16(so + 2 * TILEB, Bh + go);                                      \
            cp16(so + 3 * TILEB, Bl + go);                                      \
        }                                                                       \
        CP_COMMIT();                                                            \
    }

    K1_LOAD(0, 0)
    for (int ch = 0; ch < 8; ch++) {
        if (ch < 7) { K1_LOAD(ch + 1, (ch + 1) & 1) CP_WAIT1(); }
        else CP_WAIT0();
        __syncthreads();
        uint32_t base = sb + (ch & 1) * 4 * TILEB;
#pragma unroll
        for (int s = 0; s < 2; s++) {
            int kl = s * 16;
            uint32_t bh[4][2], bl[4][2];
#pragma unroll
            for (int ni = 0; ni < 4; ni++) {
                uint32_t off = ((wn * 32 + ni * 8 + bR) * ST + kl + bC) * 2;
                ldsm2(bh[ni], base + 2 * TILEB + off);
                ldsm2(bl[ni], base + 3 * TILEB + off);
            }
#pragma unroll
            for (int mi = 0; mi < 4; mi++) {
                uint32_t off = ((wm * 64 + mi * 16 + aR) * ST + kl + aC) * 2;
                uint32_t ah[4], al[4];
                ldsm4(ah, base + off);
                ldsm4(al, base + TILEB + off);
#pragma unroll
                for (int ni = 0; ni < 4; ni++) {
                    MMA16816(acc[mi][ni], ah, bh[ni]);
                    MMA16816(acc[mi][ni], al, bh[ni]);
                    MMA16816(acc[mi][ni], ah, bl[ni]);
                }
            }
        }
        __syncthreads();
    }

    // ---- epilogue: sim -> E, splits, partial sums ----
    float scv[4][2]; int cmv[4][2]; int crow[4][2];
#pragma unroll
    for (int mi = 0; mi < 4; mi++)
#pragma unroll
        for (int h = 0; h < 2; h++) {
            int c = cblk + wm * 64 + mi * 16 + g + h * 8;
            crow[mi][h] = c;
            scv[mi][h] = g_sc[b * LC + c];
            cmv[mi][h] = g_cm[b * LC + c];
        }
    float sqv[4][2]; int qmv[4][2]; int qcol[4];
#pragma unroll
    for (int ni = 0; ni < 4; ni++) {
        int q = qblk + wn * 32 + ni * 8 + qi * 2;
        qcol[ni] = q;
        sqv[ni][0] = g_sq[b * LQ + q];     qmv[ni][0] = g_qm[b * LQ + q];
        sqv[ni][1] = g_sq[b * LQ + q + 1]; qmv[ni][1] = g_qm[b * LQ + q + 1];
    }

    float rowp[4][2]; float colp[4][2];
#pragma unroll
    for (int i = 0; i < 4; i++) { rowp[i][0] = rowp[i][1] = colp[i][0] = colp[i][1] = 0.f; }

#pragma unroll
    for (int mi = 0; mi < 4; mi++)
#pragma unroll
        for (int ni = 0; ni < 4; ni++) {
            float e[4];
#pragma unroll
            for (int r = 0; r < 4; r++) {
                int h = r >> 1, jj = r & 1;
                float sv = acc[mi][ni][r] + scv[mi][h] + sqv[ni][jj];
                e[r] = (cmv[mi][h] | qmv[ni][jj]) ? 0.f : __expf(sv);
            }
            rowp[mi][0] += e[0] + e[1];
            rowp[mi][1] += e[2] + e[3];
            colp[ni][0] += e[0] + e[2];
            colp[ni][1] += e[1] + e[3];
#pragma unroll
            for (int h = 0; h < 2; h++) {
                __nv_bfloat162 hh, ll;
                split2(e[h * 2], e[h * 2 + 1], hh, ll);
                size_t idx = (size_t)(b * LC + crow[mi][h]) * LQ + qcol[ni];
                *(__nv_bfloat162*)(g_Eh + idx) = hh;
                *(__nv_bfloat162*)(g_El + idx) = ll;
            }
        }

#pragma unroll
    for (int mi = 0; mi < 4; mi++)
#pragma unroll
        for (int h = 0; h < 2; h++) {
            float v = rowp[mi][h];
            v += __shfl_xor_sync(0xffffffffu, v, 1);
            v += __shfl_xor_sync(0xffffffffu, v, 2);
            if (qi == 0) s_rp[wn][wm * 64 + mi * 16 + g + h * 8] = v;
        }
#pragma unroll
    for (int ni = 0; ni < 4; ni++)
#pragma unroll
        for (int jj = 0; jj < 2; jj++) {
            float v = colp[ni][jj];
            v += __shfl_xor_sync(0xffffffffu, v, 4);
            v += __shfl_xor_sync(0xffffffffu, v, 8);
            v += __shfl_xor_sync(0xffffffffu, v, 16);
            if (lane < 4) s_cp[wm][wn * 32 + ni * 8 + qi * 2 + jj] = v;
        }
    __syncthreads();
    if (tid < 128) {
        float r = s_rp[0][tid] + s_rp[1][tid] + s_rp[2][tid] + s_rp[3][tid];
        g_rowsum_part[((size_t)b * 2 + blockIdx.y) * LC + cblk + tid] = r;
        float cs = s_cp[0][tid] + s_cp[1][tid];
        g_colsum_part[((size_t)b * 16 + blockIdx.x) * LQ + qblk + tid] = cs;
    }
}

// ---------------- K2: deterministic partial reductions ----------------
__global__ void k2_reduce() {
    int b = blockIdx.x, tid = threadIdx.x;
    for (int c = tid; c < LC; c += 256) {
        float rs = g_rowsum_part[((size_t)b * 2 + 0) * LC + c] +
                   g_rowsum_part[((size_t)b * 2 + 1) * LC + c];
        g_invrow[b * LC + c] = rs > 0.f ? 1.0f / rs : 0.f;
    }
    {
        int q = tid;
        float s = 0.f;
#pragma unroll
        for (int t = 0; t < 16; t++) s += g_colsum_part[((size_t)b * 16 + t) * LQ + q];
        g_colsum[b * LQ + q] = s;
    }
    {
        int d = tid;
        float s = 0.f;
#pragma unroll
        for (int t = 0; t < 8; t++) s += g_cmean_part[((size_t)b * 8 + t) * Dd + d];
        g_cmean[b * Dd + d] = s * (1.0f / LC);
    }
}

// ============================================================================
// K3 (HMMA + trans-ldmatrix + cp.async + split-K x4)
// Tpart[ks] = sum_{c in split ks} E[c][q]*ctx[c][d]
// ============================================================================
__global__ __launch_bounds__(256, 2)
void k3_mma() {
    extern __shared__ __nv_bfloat16 dyn3[];
    uint32_t sb = (uint32_t)__cvta_generic_to_shared(dyn3);

    int tid = threadIdx.x, wid = tid >> 5, lane = tid & 31;
    int b = blockIdx.z & 31;
    int ks = blockIdx.z >> 5;      // 0..3 split-k
    int qblk = blockIdx.x * 128;   // m (q)
    int dblk = blockIdx.y * 128;   // n (d)

    const __nv_bfloat16* Eh = g_Eh + (size_t)b * LC * LQ;
    const __nv_bfloat16* El = g_El + (size_t)b * LC * LQ;
    const __nv_bfloat16* Ch = g_ch + (size_t)b * LC * Dd;
    const __nv_bfloat16* Cl = g_cl + (size_t)b * LC * Dd;

    int wm = wid & 1, wn = wid >> 1;
    int g = lane >> 2, qi = lane & 3;

    int aKr = (lane & 7) + (((lane >> 4) & 1) << 3);
    int aMc = (((lane >> 3) & 1) << 3);
    int bKr = lane & 15;

    float acc[4][4][4];
#pragma unroll
    for (int mi = 0; mi < 4; mi++)
#pragma unroll
        for (int ni = 0; ni < 4; ni++)
#pragma unroll
            for (int r = 0; r < 4; r++) acc[mi][ni][r] = 0.f;

#define K3_LOAD(ko_, stg)                                                       \
    {                                                                           \
        uint32_t sbase_ = sb + (stg) * 4 * TILE3B;                              \
        _Pragma("unroll")                                                       \
        for (int j = 0; j < 2; j++) {                                           \
            int cid = tid * 2 + j;                                              \
            int row = cid >> 4, c8 = (cid & 15) * 8;                            \
            uint32_t so = sbase_ + (row * ST3 + c8) * 2;                        \
            size_t gq = (size_t)((ko_) + row) * LQ + qblk + c8;                 \
            size_t gd = (size_t)((ko_) + row) * Dd + dblk + c8;                 \
            cp16(so, Eh + gq);                                                  \
            cp16(so + TILE3B, El + gq);                                         \
            cp16(so + 2 * TILE3B, Ch + gd);                                     \
            cp16(so + 3 * TILE3B, Cl + gd);                                     \
        }                                                                       \
        CP_COMMIT();                                                            \
    }

    int kbase = ks * 512;
    K3_LOAD(kbase, 0)
    for (int ch = 0; ch < 16; ch++) {
        if (ch < 15) { K3_LOAD(kbase + (ch + 1) * 32, (ch + 1) & 1) CP_WAIT1(); }
        else CP_WAIT0();
        __syncthreads();
        uint32_t base = sb + (ch & 1) * 4 * TILE3B;
#pragma unroll
        for (int s = 0; s < 2; s++) {
            int kl = s * 16;
            uint32_t bh[4][2], bl[4][2];
#pragma unroll
            for (int ni = 0; ni < 4; ni++) {
                uint32_t off = ((kl + bKr) * ST3 + wn * 32 + ni * 8) * 2;
                ldsm2t(bh[ni], base + 2 * TILE3B + off);
                ldsm2t(bl[ni], base + 3 * TILE3B + off);
            }
#pragma unroll
            for (int mi = 0; mi < 4; mi++) {
                uint32_t off = ((kl + aKr) * ST3 + wm * 64 + mi * 16 + aMc) * 2;
                uint32_t ah[4], al[4];
                ldsm4t(ah, base + off);
                ldsm4t(al, base + TILE3B + off);
#pragma unroll
                for (int ni = 0; ni < 4; ni++) {
                    MMA16816(acc[mi][ni], ah, bh[ni]);
                    MMA16816(acc[mi][ni], al, bh[ni]);
                    MMA16816(acc[mi][ni], ah, bl[ni]);
                }
            }
        }
        __syncthreads();
    }

    // raw partials out (no scaling)
    float* tp = g_Tpart + (((size_t)ks * Bb + b) * LQ) * Dd;
#pragma unroll
    for (int ni = 0; ni < 4; ni++) {
        int d = dblk + wn * 32 + ni * 8 + qi * 2;
#pragma unroll
        for (int mi = 0; mi < 4; mi++) {
            int q0 = qblk + wm * 64 + mi * 16 + g;
            int q1 = q0 + 8;
            *(float2*)(tp + (size_t)q0 * Dd + d) = make_float2(acc[mi][ni][0], acc[mi][ni][1]);
            *(float2*)(tp + (size_t)q1 * Dd + d) = make_float2(acc[mi][ni][2], acc[mi][ni][3]);
        }
    }
}

// ---------------- K3r: reduce split-k, scale, fallback, emit fp32 + bf16 splits -------
__global__ void k3_reduce() {
    int q = blockIdx.x, b = blockIdx.y, d = threadIdx.x;
    size_t o = ((size_t)b * LQ + q) * Dd + d;
    size_t stride = (size_t)Bb * LQ * Dd;
    float s = g_Tpart[o] + g_Tpart[o + stride] + g_Tpart[o + 2 * stride] + g_Tpart[o + 3 * stride];
    float cs = g_colsum[b * LQ + q];
    float v = cs > 0.f ? s * (1.0f / cs) : g_cmean[b * Dd + d];
    g_T[o] = v;
    __nv_bfloat16 h = __float2bfloat16(v);
    g_Th[o] = h;
    g_Tl[o] = __float2bfloat16(v - __bfloat162float(h));
}

// ---------------- K3b: tmean = mean_q T ----------------
__global__ void k3b_tmean() {
    int b = blockIdx.x, d = threadIdx.x;
    const float* p = g_T + (size_t)b * LQ * Dd + d;
    float s0 = 0, s1 = 0, s2 = 0, s3 = 0;
    for (int q = 0; q < LQ; q += 4) {
        s0 += p[(size_t)(q + 0) * Dd]; s1 += p[(size_t)(q + 1) * Dd];
        s2 += p[(size_t)(q + 2) * Dd]; s3 += p[(size_t)(q + 3) * Dd];
    }
    g_tmean[b * Dd + d] = ((s0 + s1) + (s2 + s3)) * (1.0f / LQ);
}

// ============================================================================
// K4 (HMMA): Out[c][d] = (1/rowsum[c]) * sum_q E[c][q] * Bsrc[q][d]
// A = E [c][q] non-trans; B = qh/Th [q][d] via trans-ldmatrix (no transpose kernels).
// ============================================================================
#define STG4B (2 * TILEB + 2 * TILE3B)   // 37888 per stage

__global__ __launch_bounds__(256, 2)
void k4_mma(float* __restrict__ out) {
    extern __shared__ __nv_bfloat16 dyn4[];
    uint32_t sb = (uint32_t)__cvta_generic_to_shared(dyn4);

    int tid = threadIdx.x, wid = tid >> 5, lane = tid & 31;
    int b = blockIdx.z;
    int cblk = blockIdx.x * 128;
    int sel = blockIdx.y >> 1;
    int dblk = (blockIdx.y & 1) * 128;

    const __nv_bfloat16* Eh = g_Eh + ((size_t)b * LC + cblk) * LQ;
    const __nv_bfloat16* El = g_El + ((size_t)b * LC + cblk) * LQ;
    const __nv_bfloat16* Qh = (sel ? g_Th : g_qh) + (size_t)b * LQ * Dd;
    const __nv_bfloat16* Ql = (sel ? g_Tl : g_ql) + (size_t)b * LQ * Dd;
    const float* fb = (sel ? g_tmean : g_qmean) + b * Dd;
    float* op = out + (size_t)sel * Bb * LC * Dd + (size_t)b * LC * Dd;

    int wm = wid & 1, wn = wid >> 1;
    int g = lane >> 2, qi = lane & 3;

    int aR = (lane & 7) + (((lane >> 3) & 1) << 3);
    int aC = (((lane >> 4) & 1) << 3);
    int bKr = lane & 15;

    float acc[4][4][4];
#pragma unroll
    for (int mi = 0; mi < 4; mi++)
#pragma unroll
        for (int ni = 0; ni < 4; ni++)
#pragma unroll
            for (int r = 0; r < 4; r++) acc[mi][ni][r] = 0.f;

#define K4_LOAD(ch, stg)                                                        \
    {                                                                           \
        int ko_ = (ch) * 32;                                                    \
        uint32_t sbase_ = sb + (stg) * STG4B;                                   \
        _Pragma("unroll")                                                       \
        for (int j = 0; j < 2; j++) {                                           \
            int cid = tid * 2 + j;                                              \
            int rowE = cid >> 2, cE = (cid & 3) * 8;                            \
            size_t goE = (size_t)rowE * LQ + ko_ + cE;                          \
            uint32_t soE = sbase_ + (rowE * ST + cE) * 2;                       \
            cp16(soE, Eh + goE);                                                \
            cp16(soE + TILEB, El + goE);                                        \
            int rowQ = cid >> 4, cQ = (cid & 15) * 8;                           \
            size_t goQ = (size_t)(ko_ + rowQ) * Dd + dblk + cQ;                 \
            uint32_t soQ = sbase_ + 2 * TILEB + (rowQ * ST3 + cQ) * 2;          \
            cp16(soQ, Qh + goQ);                                                \
            cp16(soQ + TILE3B, Ql + goQ);                                       \
        }                                                                       \
        CP_COMMIT();                                                            \
    }

    K4_LOAD(0, 0)
    for (int ch = 0; ch < 8; ch++) {
        if (ch < 7) { K4_LOAD(ch + 1, (ch + 1) & 1) CP_WAIT1(); }
        else CP_WAIT0();
        __syncthreads();
        uint32_t base = sb + (ch & 1) * STG4B;
#pragma unroll
        for (int s = 0; s < 2; s++) {
            int kl = s * 16;
            uint32_t bh[4][2], bl[4][2];
#pragma unroll
            for (int ni = 0; ni < 4; ni++) {
                uint32_t off = ((kl + bKr) * ST3 + wn * 32 + ni * 8) * 2;
                ldsm2t(bh[ni], base + 2 * TILEB + off);
                ldsm2t(bl[ni], base + 2 * TILEB + TILE3B + off);
            }
#pragma unroll
            for (int mi = 0; mi < 4; mi++) {
                uint32_t off = ((wm * 64 + mi * 16 + aR) * ST + kl + aC) * 2;
                uint32_t ah[4], al[4];
                ldsm4(ah, base + off);
                ldsm4(al, base + TILEB + off);
#pragma unroll
                for (int ni = 0; ni < 4; ni++) {
                    MMA16816(acc[mi][ni], ah, bh[ni]);
                    MMA16816(acc[mi][ni], al, bh[ni]);
                    MMA16816(acc[mi][ni], ah, bl[ni]);
                }
            }
        }
        __syncthreads();
    }

#pragma unroll
    for (int ni = 0; ni < 4; ni++) {
        int dcol = dblk + wn * 32 + ni * 8 + qi * 2;
        float fb0 = fb[dcol], fb1 = fb[dcol + 1];
#pragma unroll
        for (int mi = 0; mi < 4; mi++) {
            int c0 = cblk + wm * 64 + mi * 16 + g;
            int c1 = c0 + 8;
            float inv0 = g_invrow[b * LC + c0];
            float inv1 = g_invrow[b * LC + c1];
            float2 v0, v1;
            if (inv0 > 0.f) { v0.x = acc[mi][ni][0] * inv0; v0.y = acc[mi][ni][1] * inv0; }
            else            { v0.x = fb0; v0.y = fb1; }
            if (inv1 > 0.f) { v1.x = acc[mi][ni][2] * inv1; v1.y = acc[mi][ni][3] * inv1; }
            else            { v1.x = fb0; v1.y = fb1; }
            *(float2*)(op + (size_t)c0 * Dd + dcol) = v0;
            *(float2*)(op + (size_t)c1 * Dd + dcol) = v1;
        }
    }
}

// ---------------- launcher ----------------
extern "C" void kernel_launch(void* const* d_in, const int* in_sizes, int n_in,
                              void* d_out, int out_size) {
    const float* ctx = (const float*)d_in[0];
    const float* qry = (const float*)d_in[1];
    const void* cmask = d_in[2];
    const void* qmask = d_in[3];
    const float* w0 = (const float*)d_in[4];
    float* out = (float*)d_out;

    const int smem1 = 2 * 4 * TILEB;    // 81920
    const int smem3 = 2 * 4 * TILE3B;   // 69632
    const int smem4 = 2 * STG4B;        // 75776
    cudaFuncSetAttribute(k1_mma, cudaFuncAttributeMaxDynamicSharedMemorySize, smem1);
    cudaFuncSetAttribute(k3_mma, cudaFuncAttributeMaxDynamicSharedMemorySize, smem3);
    cudaFuncSetAttribute(k4_mma, cudaFuncAttributeMaxDynamicSharedMemorySize, smem4);

    k_detect<<<1, 32>>>((const unsigned char*)cmask);
    k_cvt_mask<<<(Bb * LC + 255) / 256, 256>>>(cmask, qmask);
    k0_rowdots<<<(Bb * (LC + LQ)) / 8, 256>>>(ctx, qry, w0);
    k0_ctx<<<dim3(Bb, 8), 256>>>(ctx);
    k0_qmean<<<Bb, 256>>>(qry);
    k_cvtQW<<<(int)(((size_t)Bb * LQ * Dd / 4) / 256), 256>>>(qry, w0);
    k1_mma<<<dim3(LC / 128, LQ / 128, Bb), 256, smem1>>>();
    k2_reduce<<<Bb, 256>>>();
    k3_mma<<<dim3(LQ / 128, Dd / 128, Bb * 4), 256, smem3>>>();
    k3_reduce<<<dim3(LQ, Bb), 256>>>();
    k3b_tmean<<<Bb, 256>>>();
    k4_mma<<<dim3(LC / 128, 4, Bb), 256, smem4>>>(out);
}